// round 12
// baseline (speedup 1.0000x reference)
#include <cuda_runtime.h>
#include <cuda_fp16.h>
#include <cstdint>

#define NB 16
#define BC 2048

#define NTILE 4                         // bc tiles per relation block
#define NCH (NTILE * 2)                 // 64-col chunks per block
#define RSTRIDE 72                      // floats per staged row (64 + 8 pad)
#define REGION_FLOATS (32 * RSTRIDE)    // one 32-row region
#define BUF_FLOATS (4 * REGION_FLOATS)  // 4 regions per buffer
#define DYN_FLOATS (2 * BUF_FLOATS + 8 * 128)
#define DYN_BYTES (DYN_FLOATS * 4)      // 77824 B

// ---------------------------------------------------------------------------
// Scratch (static device globals)
// ---------------------------------------------------------------------------
__device__ float g_base_thorn[BC * 128];
__device__ float g_A1[BC * 128];
__device__ float g_A2[BC * 128];
__device__ float g_thorn_agg[BC * 128];
__device__ float g_clone_agg[BC * 128];
// Prepacked fp16 B fragments for mma.m16n8k16, nt-pairs adjacent.
// 9 matrices: 0=W_thorn[:H], 1=W_clone[:H], 2=W_clone[H:2H],
//             3=W_thorn[H:2H], 4=W_clone[2H:3H], 5..8=W_agg slices.
__device__ uint32_t g_Bpack[9][8192];

// ---------------------------------------------------------------------------
// Prepack all weights into fp16 fragment order.
// ---------------------------------------------------------------------------
__global__ void __launch_bounds__(256) prepack_b_kernel(
    const float* __restrict__ W_thorn,
    const float* __restrict__ W_clone,
    const float* __restrict__ W_agg)
{
    int gidx = blockIdx.x * 256 + threadIdx.x;    // 0 .. 9*8192-1
    int m = gidx >> 13;
    int idx = gidx & 8191;
    const float* W;
    switch (m) {
        case 0: W = W_thorn; break;
        case 1: W = W_clone; break;
        case 2: W = W_clone + 16384; break;
        case 3: W = W_thorn + 16384; break;
        case 4: W = W_clone + 32768; break;
        default: W = W_agg + (m - 5) * 16384; break;
    }
    int j    = idx & 3;
    int lane = (idx >> 2) & 31;
    int ntp  = (idx >> 7) & 7;
    int ks   = idx >> 10;
    int t4 = lane & 3, g = lane >> 2;
    int nt = 2 * ntp + (j >> 1);
    int k = ks * 16 + (j & 1) * 8 + 2 * t4;
    int n = nt * 8 + g;
    __half2 h = __floats2half2_rn(W[k * 128 + n], W[(k + 1) * 128 + n]);
    g_Bpack[m][idx] = *(uint32_t*)&h;
}

// ---------------------------------------------------------------------------
// MMA helpers
// ---------------------------------------------------------------------------
__device__ __forceinline__ void mma2(const uint4& bb,
                                     uint32_t a0, uint32_t a1, uint32_t a2, uint32_t a3,
                                     float* acc0, float* acc1) {
    asm volatile(
        "mma.sync.aligned.m16n8k16.row.col.f32.f16.f16.f32 "
        "{%0,%1,%2,%3}, {%4,%5,%6,%7}, {%8,%9}, {%0,%1,%2,%3};"
        : "+f"(acc0[0]), "+f"(acc0[1]), "+f"(acc0[2]), "+f"(acc0[3])
        : "r"(a0), "r"(a1), "r"(a2), "r"(a3), "r"(bb.x), "r"(bb.y));
    asm volatile(
        "mma.sync.aligned.m16n8k16.row.col.f32.f16.f16.f32 "
        "{%0,%1,%2,%3}, {%4,%5,%6,%7}, {%8,%9}, {%0,%1,%2,%3};"
        : "+f"(acc1[0]), "+f"(acc1[1]), "+f"(acc1[2]), "+f"(acc1[3])
        : "r"(a0), "r"(a1), "r"(a2), "r"(a3), "r"(bb.z), "r"(bb.w));
}

// Warp-level GEMM accumulate over ks steps [ks0, ks0+nks), A fp32 in gmem.
__device__ __forceinline__ void mma_acc_gmem(
    const float* __restrict__ A0,
    const uint32_t* __restrict__ Bp,
    float acc[16][4], int lane, int ks0, int nks)
{
    const int g = lane >> 2, t4 = lane & 3;
    const float* p0 = A0 + g * 128 + ks0 * 16 + 2 * t4;
    const float* p1 = A0 + (g + 8) * 128 + ks0 * 16 + 2 * t4;
    float2 f00 = *(const float2*)(p0);
    float2 f10 = *(const float2*)(p1);
    float2 f01 = *(const float2*)(p0 + 8);
    float2 f11 = *(const float2*)(p1 + 8);
#pragma unroll
    for (int kk = 0; kk < 8; kk++) {
        if (kk >= nks) break;
        __half2 h;
        uint32_t a0, a1, a2, a3;
        h = __floats2half2_rn(f00.x, f00.y); a0 = *(uint32_t*)&h;
        h = __floats2half2_rn(f10.x, f10.y); a1 = *(uint32_t*)&h;
        h = __floats2half2_rn(f01.x, f01.y); a2 = *(uint32_t*)&h;
        h = __floats2half2_rn(f11.x, f11.y); a3 = *(uint32_t*)&h;
        if (kk + 1 < nks) {
            f00 = *(const float2*)(p0 + 16 * (kk + 1));
            f10 = *(const float2*)(p1 + 16 * (kk + 1));
            f01 = *(const float2*)(p0 + 16 * (kk + 1) + 8);
            f11 = *(const float2*)(p1 + 16 * (kk + 1) + 8);
        }
        const uint32_t* bbase = Bp + (ks0 + kk) * 1024 + lane * 4;
#pragma unroll
        for (int ntp = 0; ntp < 8; ntp++) {
            uint4 bb = *(const uint4*)&bbase[ntp * 128];
            mma2(bb, a0, a1, a2, a3, acc[2 * ntp], acc[2 * ntp + 1]);
        }
    }
}

__device__ __forceinline__ void zero16(float acc[16][4]) {
#pragma unroll
    for (int nt = 0; nt < 16; nt++)
#pragma unroll
        for (int c = 0; c < 4; c++) acc[nt][c] = 0.0f;
}

__device__ __forceinline__ void cp_async16s(uint32_t dst, const float* src) {
    asm volatile("cp.async.cg.shared.global [%0], [%1], 16;"
                 :: "r"(dst), "l"(__cvta_generic_to_global(src)));
}

// ---------------------------------------------------------------------------
// Precompute: clone @ {W_thorn[:H], W_clone[:H], W_clone[H:2H]}
// ---------------------------------------------------------------------------
__global__ void __launch_bounds__(128) precompute_kernel(
    const float* __restrict__ clone)
{
    const int tid = threadIdx.x;
    const int warp = tid >> 5;
    const int lane = tid & 31;
    const int y = blockIdx.y;
    const int m0 = blockIdx.x * 64 + warp * 16;

    float* out = (y == 0) ? g_base_thorn : (y == 1) ? g_A1 : g_A2;

    float acc[16][4];
    zero16(acc);
    mma_acc_gmem(clone + (size_t)m0 * 128, g_Bpack[y], acc, lane, 0, 8);

    const int g = lane >> 2, t4 = lane & 3;
    const int r0 = m0 + g, r1 = r0 + 8;
#pragma unroll
    for (int nt = 0; nt < 16; nt++) {
        const int n0 = nt * 8 + 2 * t4;
        *(float2*)&out[(size_t)r0 * 128 + n0] = make_float2(acc[nt][0], acc[nt][1]);
        *(float2*)&out[(size_t)r1 * 128 + n0] = make_float2(acc[nt][2], acc[nt][3]);
    }
}

// ---------------------------------------------------------------------------
// Relation kernel: one block per (4 bc tiles, branch). 256 threads = 8 warps.
// Warp (p = w&3, cg = w>>2): rows p*32..+32, cols cg*64..+64 of each tile.
// A staged fp32 via cp.async in 64-col chunks, double-buffered, pipelined
// ACROSS tile boundaries with pair-local named barriers. cp.async never
// stalls the issuing warp, so DRAM latency hides behind MMA of the previous
// chunk; epilogue block-syncs don't drain in-flight loads.
// ---------------------------------------------------------------------------
__global__ void __launch_bounds__(256) relation_mma_kernel(
    const float* __restrict__ thorn_rel,
    const float* __restrict__ clone_rel,
    const float* __restrict__ b_thorn,
    const float* __restrict__ b_clone,
    const int* __restrict__ thorn_mask,
    const int* __restrict__ clone_mask)
{
    extern __shared__ float sdyn[];
    float* red = sdyn + 2 * BUF_FLOATS;

    const int tid = threadIdx.x;
    const int warp = tid >> 5;
    const int lane = tid & 31;
    const int g = lane >> 2;
    const int t4 = lane & 3;
    const int p  = warp & 3;        // row group
    const int cg = warp >> 2;       // col group
    const int branch = blockIdx.y;
    const int bc_base = blockIdx.x * NTILE;
    const int b = bc_base >> 7;     // constant within block (NTILE | 128)

    const float* rel = branch ? clone_rel : thorn_rel;
    const float* bias = branch ? b_clone : b_thorn;
    const int* mask = branch ? clone_mask : thorn_mask;
    const float* baseCol = branch ? g_A1 : g_base_thorn;
    float* out = branch ? g_clone_agg : g_thorn_agg;
    const uint32_t* __restrict__ Bp = g_Bpack[3 + branch];

    uint32_t sbase;
    asm("{ .reg .u64 t; cvta.to.shared.u64 t, %1; cvt.u32.u64 %0, t; }"
        : "=r"(sbase) : "l"((const void*)sdyn));

    // Staging dst base per buffer for this warp (region p, rows cg*16..)
    uint32_t wstage[2];
    wstage[0] = sbase + (uint32_t)((0 * 4 + p) * REGION_FLOATS + cg * 16 * RSTRIDE) * 4;
    wstage[1] = sbase + (uint32_t)((1 * 4 + p) * REGION_FLOATS + cg * 16 * RSTRIDE) * 4;
    // Compute read base per buffer (region p, row 0)
    const float* rbase[2] = { sdyn + (0 * 4 + p) * REGION_FLOATS,
                              sdyn + (1 * 4 + p) * REGION_FLOATS };

    const float* Ablock = rel + (size_t)bc_base * 16384;

    // Masks / row-term pointers (rows constant across tiles; b constant)
    const int wr = p * 32;
    int rowi[4] = {wr + g, wr + g + 8, wr + 16 + g, wr + 24 + g};
    float mk[4];
    const float* rtp[4];
#pragma unroll
    for (int q = 0; q < 4; q++) {
        mk[q] = (float)mask[b * 128 + rowi[q]];
        rtp[q] = g_A2 + ((size_t)(b * 128 + rowi[q])) * 128;
    }
    const int c0col = cg * 64;

    // Stage chunk c (tile c>>1, col half c&1) -> buffer (c&1).
    auto stage = [&](int c) {
        const int t = c >> 1, h = c & 1;
        const float* src = Ablock + (size_t)t * 16384
                         + (size_t)(p * 32 + cg * 16) * 128 + h * 64;
        const uint32_t dst = wstage[h];
#pragma unroll
        for (int u = 0; u < 8; u++) {
            int l = lane + u * 32;          // 0..255
            int row = l >> 4, j = l & 15;
            cp_async16s(dst + (uint32_t)(row * RSTRIDE + j * 4) * 4,
                        src + row * 128 + j * 4);
        }
        asm volatile("cp.async.commit_group;" ::: "memory");
    };

    float acc[2][8][4];
#pragma unroll
    for (int mt = 0; mt < 2; mt++)
#pragma unroll
        for (int nt = 0; nt < 8; nt++)
#pragma unroll
            for (int c = 0; c < 4; c++) acc[mt][nt][c] = 0.0f;

    stage(0);
    stage(1);

#pragma unroll
    for (int c = 0; c < NCH; c++) {
        // Wait for chunk c (this thread's oldest group); keep c+1 in flight.
        if (c < NCH - 1) asm volatile("cp.async.wait_group 1;" ::: "memory");
        else             asm volatile("cp.async.wait_group 0;" ::: "memory");
        asm volatile("bar.sync %0, 64;" :: "r"(p + 1) : "memory");   // pair: data visible

        const int h = c & 1;
        const float* rb = rbase[h];
#pragma unroll
        for (int ksl = 0; ksl < 4; ksl++) {
            const int ks = h * 4 + ksl;
            uint32_t af[2][4];
#pragma unroll
            for (int mt = 0; mt < 2; mt++) {
                float2 f00 = *(const float2*)&rb[(mt * 16 + g) * RSTRIDE + ksl * 16 + 2 * t4];
                float2 f10 = *(const float2*)&rb[(mt * 16 + g + 8) * RSTRIDE + ksl * 16 + 2 * t4];
                float2 f01 = *(const float2*)&rb[(mt * 16 + g) * RSTRIDE + ksl * 16 + 2 * t4 + 8];
                float2 f11 = *(const float2*)&rb[(mt * 16 + g + 8) * RSTRIDE + ksl * 16 + 2 * t4 + 8];
                __half2 hh;
                hh = __floats2half2_rn(f00.x, f00.y); af[mt][0] = *(uint32_t*)&hh;
                hh = __floats2half2_rn(f10.x, f10.y); af[mt][1] = *(uint32_t*)&hh;
                hh = __floats2half2_rn(f01.x, f01.y); af[mt][2] = *(uint32_t*)&hh;
                hh = __floats2half2_rn(f11.x, f11.y); af[mt][3] = *(uint32_t*)&hh;
            }
            const uint32_t* bbase = Bp + ks * 1024 + cg * 512 + lane * 4;
#pragma unroll
            for (int ntp = 0; ntp < 4; ntp++) {
                uint4 bb = *(const uint4*)&bbase[ntp * 128];
                mma2(bb, af[0][0], af[0][1], af[0][2], af[0][3],
                     acc[0][2 * ntp], acc[0][2 * ntp + 1]);
                mma2(bb, af[1][0], af[1][1], af[1][2], af[1][3],
                     acc[1][2 * ntp], acc[1][2 * ntp + 1]);
            }
        }
        asm volatile("bar.sync %0, 64;" :: "r"(p + 1) : "memory");   // pair done reading buf h

        if (c + 2 < NCH) stage(c + 2);     // refill buffer h for tile t+1

        if (c & 1) {
            // ---- Epilogue for tile t = c>>1 ----
            const int t = c >> 1;
            const int bc = bc_base + t;
#pragma unroll
            for (int nt = 0; nt < 8; nt++) {
                const int n0 = c0col + nt * 8 + 2 * t4;
                float2 bs = *(const float2*)&baseCol[(size_t)bc * 128 + n0];
                float2 bi = *(const float2*)&bias[n0];
                float add0 = bs.x + bi.x;
                float add1 = bs.y + bi.y;
                float c0m = 0.0f, c1m = 0.0f;
#pragma unroll
                for (int mt = 0; mt < 2; mt++) {
                    float x0 = acc[mt][nt][0] + add0;
                    float x1 = acc[mt][nt][1] + add1;
                    float x2 = acc[mt][nt][2] + add0;
                    float x3 = acc[mt][nt][3] + add1;
                    if (branch) {
                        float2 ra = *(const float2*)&rtp[mt * 2][n0];
                        float2 rbb = *(const float2*)&rtp[mt * 2 + 1][n0];
                        x0 += ra.x; x1 += ra.y;
                        x2 += rbb.x; x3 += rbb.y;
                    }
                    float ma = mk[mt * 2], mb = mk[mt * 2 + 1];
                    c0m = fmaxf(c0m, fmaxf(fmaxf(x0, 0.0f) * ma, fmaxf(x2, 0.0f) * mb));
                    c1m = fmaxf(c1m, fmaxf(fmaxf(x1, 0.0f) * ma, fmaxf(x3, 0.0f) * mb));
                }
#pragma unroll
                for (int off = 4; off < 32; off <<= 1) {
                    c0m = fmaxf(c0m, __shfl_xor_sync(0xFFFFFFFFu, c0m, off));
                    c1m = fmaxf(c1m, __shfl_xor_sync(0xFFFFFFFFu, c1m, off));
                }
                if (g == 0) {
                    red[warp * 128 + n0] = c0m;
                    red[warp * 128 + n0 + 1] = c1m;
                }
            }
            __syncthreads();
            if (tid < 128) {
                int wb = (tid >> 6) * 4;
                float m = fmaxf(fmaxf(red[(wb + 0) * 128 + tid], red[(wb + 1) * 128 + tid]),
                                fmaxf(red[(wb + 2) * 128 + tid], red[(wb + 3) * 128 + tid]));
                out[(size_t)bc * 128 + tid] = m;
            }
            __syncthreads();
            // Zero accumulators for next tile
#pragma unroll
            for (int mt = 0; mt < 2; mt++)
#pragma unroll
                for (int nt = 0; nt < 8; nt++)
#pragma unroll
                    for (int cc = 0; cc < 4; cc++) acc[mt][nt][cc] = 0.0f;
        }
    }
}

// ---------------------------------------------------------------------------
// Fused final: out = clone + relu([clone|food|thorn_agg|clone_agg] @ W_agg + b)
// Grid 128, 256 threads = 8 warps; warp w handles slice s = w>>1,
// K-half kh = w&1. Two-phase accumulation into 4 shared buffers (32 KB).
// ---------------------------------------------------------------------------
__global__ void __launch_bounds__(256) final_kernel(
    const float* __restrict__ clone,
    const float* __restrict__ food,
    const float* __restrict__ b_agg,
    float* __restrict__ out)
{
    __shared__ float sacc[4][16 * 128];     // 32 KB

    const int tid = threadIdx.x;
    const int warp = tid >> 5;
    const int lane = tid & 31;
    const int m0 = blockIdx.x * 16;
    const int s = warp >> 1;
    const int kh = warp & 1;

    const float* src = (s == 0) ? clone : (s == 1) ? food
                     : (s == 2) ? g_thorn_agg : g_clone_agg;

    float acc[16][4];
    zero16(acc);
    mma_acc_gmem(src + (size_t)m0 * 128, g_Bpack[5 + s], acc, lane, kh * 4, 4);

    const int g = lane >> 2, t4 = lane & 3;
    if (kh == 0) {
#pragma unroll
        for (int nt = 0; nt < 16; nt++) {
            const int n0 = nt * 8 + 2 * t4;
            *(float2*)&sacc[s][g * 128 + n0]       = make_float2(acc[nt][0], acc[nt][1]);
            *(float2*)&sacc[s][(g + 8) * 128 + n0] = make_float2(acc[nt][2], acc[nt][3]);
        }
    }
    __syncthreads();
    if (kh == 1) {
#pragma unroll
        for (int nt = 0; nt < 16; nt++) {
            const int n0 = nt * 8 + 2 * t4;
            float2 u0 = *(float2*)&sacc[s][g * 128 + n0];
            float2 u1 = *(float2*)&sacc[s][(g + 8) * 128 + n0];
            u0.x += acc[nt][0]; u0.y += acc[nt][1];
            u1.x += acc[nt][2]; u1.y += acc[nt][3];
            *(float2*)&sacc[s][g * 128 + n0]       = u0;
            *(float2*)&sacc[s][(g + 8) * 128 + n0] = u1;
        }
    }
    __syncthreads();

#pragma unroll
    for (int i = 0; i < 8; i++) {
        int e = tid + i * 256;            // 0..2047
        int r = e >> 7, n = e & 127;
        float ssum = sacc[0][e] + sacc[1][e] + sacc[2][e] + sacc[3][e] + b_agg[n];
        size_t o = (size_t)(m0 + r) * 128 + n;
        out[o] = clone[o] + fmaxf(ssum, 0.0f);
    }
}

// ---------------------------------------------------------------------------
// Launch
// ---------------------------------------------------------------------------
extern "C" void kernel_launch(void* const* d_in, const int* in_sizes, int n_in,
                              void* d_out, int out_size)
{
    const float* food       = (const float*)d_in[0];
    const float* thorn_rel  = (const float*)d_in[1];
    const float* clone      = (const float*)d_in[2];
    const float* clone_rel  = (const float*)d_in[3];
    const int*   thorn_mask = (const int*)d_in[4];
    const int*   clone_mask = (const int*)d_in[5];
    const float* W_thorn    = (const float*)d_in[6];
    const float* b_thorn    = (const float*)d_in[7];
    const float* W_clone    = (const float*)d_in[8];
    const float* b_clone    = (const float*)d_in[9];
    const float* W_agg      = (const float*)d_in[10];
    const float* b_agg      = (const float*)d_in[11];
    float* out = (float*)d_out;

    static bool attr_set = false;
    if (!attr_set) {
        cudaFuncSetAttribute(relation_mma_kernel,
                             cudaFuncAttributeMaxDynamicSharedMemorySize, DYN_BYTES);
        attr_set = true;
    }

    prepack_b_kernel<<<288, 256>>>(W_thorn, W_clone, W_agg);
    precompute_kernel<<<dim3(32, 3), 128>>>(clone);
    relation_mma_kernel<<<dim3(BC / NTILE, 2), 256, DYN_BYTES>>>(
        thorn_rel, clone_rel, b_thorn, b_clone, thorn_mask, clone_mask);
    final_kernel<<<128, 256>>>(clone, food, b_agg, out);
}

// round 13
// speedup vs baseline: 1.0877x; 1.0877x over previous
#include <cuda_runtime.h>
#include <cuda_fp16.h>
#include <cstdint>

#define NB 16
#define BC 2048
#define WSTRIDE 272   // bytes per A row in smem region (256 data + 16 pad)

// ---------------------------------------------------------------------------
// Scratch (static device globals)
// ---------------------------------------------------------------------------
__device__ float g_base_thorn[BC * 128];
__device__ float g_A1[BC * 128];
__device__ float g_A2[BC * 128];
__device__ float g_thorn_agg[BC * 128];
__device__ float g_clone_agg[BC * 128];
// Prepacked fp16 B fragments for mma.m16n8k16, nt-pairs adjacent.
// 9 matrices: 0=W_thorn[:H], 1=W_clone[:H], 2=W_clone[H:2H],
//             3=W_thorn[H:2H], 4=W_clone[2H:3H], 5..8=W_agg slices.
// layout [m][ ((ks*8 + ntp)*32 + lane)*4 + j ]  -> 8192 u32 per matrix
__device__ uint32_t g_Bpack[9][8192];

// ---------------------------------------------------------------------------
// Prepack all weights into fp16 fragment order.
// ---------------------------------------------------------------------------
__global__ void __launch_bounds__(256) prepack_b_kernel(
    const float* __restrict__ W_thorn,
    const float* __restrict__ W_clone,
    const float* __restrict__ W_agg)
{
    int gidx = blockIdx.x * 256 + threadIdx.x;    // 0 .. 9*8192-1
    int m = gidx >> 13;
    int idx = gidx & 8191;
    const float* W;
    switch (m) {
        case 0: W = W_thorn; break;
        case 1: W = W_clone; break;
        case 2: W = W_clone + 16384; break;
        case 3: W = W_thorn + 16384; break;
        case 4: W = W_clone + 32768; break;
        default: W = W_agg + (m - 5) * 16384; break;
    }
    int j    = idx & 3;
    int lane = (idx >> 2) & 31;
    int ntp  = (idx >> 7) & 7;
    int ks   = idx >> 10;
    int t4 = lane & 3, g = lane >> 2;
    int nt = 2 * ntp + (j >> 1);
    int k = ks * 16 + (j & 1) * 8 + 2 * t4;
    int n = nt * 8 + g;
    __half2 h = __floats2half2_rn(W[k * 128 + n], W[(k + 1) * 128 + n]);
    g_Bpack[m][idx] = *(uint32_t*)&h;
}

// ---------------------------------------------------------------------------
// MMA helpers
// ---------------------------------------------------------------------------
__device__ __forceinline__ void mma2(const uint4& bb,
                                     uint32_t a0, uint32_t a1, uint32_t a2, uint32_t a3,
                                     float* acc0, float* acc1) {
    asm volatile(
        "mma.sync.aligned.m16n8k16.row.col.f32.f16.f16.f32 "
        "{%0,%1,%2,%3}, {%4,%5,%6,%7}, {%8,%9}, {%0,%1,%2,%3};"
        : "+f"(acc0[0]), "+f"(acc0[1]), "+f"(acc0[2]), "+f"(acc0[3])
        : "r"(a0), "r"(a1), "r"(a2), "r"(a3), "r"(bb.x), "r"(bb.y));
    asm volatile(
        "mma.sync.aligned.m16n8k16.row.col.f32.f16.f16.f32 "
        "{%0,%1,%2,%3}, {%4,%5,%6,%7}, {%8,%9}, {%0,%1,%2,%3};"
        : "+f"(acc1[0]), "+f"(acc1[1]), "+f"(acc1[2]), "+f"(acc1[3])
        : "r"(a0), "r"(a1), "r"(a2), "r"(a3), "r"(bb.z), "r"(bb.w));
}

// A-tile load: stream-through (no L1 allocation) so B fragments stay L1-resident.
__device__ __forceinline__ float4 ldg_stream(const float4* p) {
    float4 v;
    asm volatile("ld.global.nc.L1::no_allocate.v4.f32 {%0,%1,%2,%3}, [%4];"
                 : "=f"(v.x), "=f"(v.y), "=f"(v.z), "=f"(v.w)
                 : "l"(__cvta_generic_to_global(p)));
    return v;
}

// Warp-level GEMM accumulate over ks steps [ks0, ks0+nks), A fp32 in gmem.
__device__ __forceinline__ void mma_acc_gmem(
    const float* __restrict__ A0,      // warp's first row; k offset ks0*16
    const uint32_t* __restrict__ Bp,
    float acc[16][4], int lane, int ks0, int nks)
{
    const int g = lane >> 2, t4 = lane & 3;
    const float* p0 = A0 + g * 128 + ks0 * 16 + 2 * t4;
    const float* p1 = A0 + (g + 8) * 128 + ks0 * 16 + 2 * t4;
    float2 f00 = *(const float2*)(p0);
    float2 f10 = *(const float2*)(p1);
    float2 f01 = *(const float2*)(p0 + 8);
    float2 f11 = *(const float2*)(p1 + 8);
#pragma unroll
    for (int kk = 0; kk < 8; kk++) {
        if (kk >= nks) break;
        __half2 h;
        uint32_t a0, a1, a2, a3;
        h = __floats2half2_rn(f00.x, f00.y); a0 = *(uint32_t*)&h;
        h = __floats2half2_rn(f10.x, f10.y); a1 = *(uint32_t*)&h;
        h = __floats2half2_rn(f01.x, f01.y); a2 = *(uint32_t*)&h;
        h = __floats2half2_rn(f11.x, f11.y); a3 = *(uint32_t*)&h;
        if (kk + 1 < nks) {
            f00 = *(const float2*)(p0 + 16 * (kk + 1));
            f10 = *(const float2*)(p1 + 16 * (kk + 1));
            f01 = *(const float2*)(p0 + 16 * (kk + 1) + 8);
            f11 = *(const float2*)(p1 + 16 * (kk + 1) + 8);
        }
        const uint32_t* bbase = Bp + (ks0 + kk) * 1024 + lane * 4;
#pragma unroll
        for (int ntp = 0; ntp < 8; ntp++) {
            uint4 bb = *(const uint4*)&bbase[ntp * 128];
            mma2(bb, a0, a1, a2, a3, acc[2 * ntp], acc[2 * ntp + 1]);
        }
    }
}

__device__ __forceinline__ void zero16(float acc[16][4]) {
#pragma unroll
    for (int nt = 0; nt < 16; nt++)
#pragma unroll
        for (int c = 0; c < 4; c++) acc[nt][c] = 0.0f;
}

// ---------------------------------------------------------------------------
// Precompute: clone @ {W_thorn[:H], W_clone[:H], W_clone[H:2H]}
// ---------------------------------------------------------------------------
__global__ void __launch_bounds__(128) precompute_kernel(
    const float* __restrict__ clone)
{
    const int tid = threadIdx.x;
    const int warp = tid >> 5;
    const int lane = tid & 31;
    const int y = blockIdx.y;
    const int m0 = blockIdx.x * 64 + warp * 16;

    float* out = (y == 0) ? g_base_thorn : (y == 1) ? g_A1 : g_A2;

    float acc[16][4];
    zero16(acc);
    mma_acc_gmem(clone + (size_t)m0 * 128, g_Bpack[y], acc, lane, 0, 8);

    const int g = lane >> 2, t4 = lane & 3;
    const int r0 = m0 + g, r1 = r0 + 8;
#pragma unroll
    for (int nt = 0; nt < 16; nt++) {
        const int n0 = nt * 8 + 2 * t4;
        *(float2*)&out[(size_t)r0 * 128 + n0] = make_float2(acc[nt][0], acc[nt][1]);
        *(float2*)&out[(size_t)r1 * 128 + n0] = make_float2(acc[nt][2], acc[nt][3]);
    }
}

// ---------------------------------------------------------------------------
// Relation kernel: one block per (bc, branch). 256 threads = 8 warps.
// Warp tiling 32 rows x 64 cols: warp w -> p = w&3 (rows p*32..+32),
// cg = w>>2 (cols cg*64..+64). Warps p and p+4 share smem region p; each
// stages 16 of the 32 rows (burst of 16 LDG.128, L1-no-allocate), pair-synced
// with named barrier p+1 (no block barrier before compute).
// ---------------------------------------------------------------------------
__global__ void __launch_bounds__(256) relation_mma_kernel(
    const float* __restrict__ thorn_rel,
    const float* __restrict__ clone_rel,
    const float* __restrict__ b_thorn,
    const float* __restrict__ b_clone,
    const int* __restrict__ thorn_mask,
    const int* __restrict__ clone_mask)
{
    __shared__ __align__(16) char sA[4][32 * WSTRIDE];   // 34816 B
    __shared__ float red[8 * 128];

    const int tid = threadIdx.x;
    const int warp = tid >> 5;
    const int lane = tid & 31;
    const int g = lane >> 2;
    const int t4 = lane & 3;
    const int p  = warp & 3;        // row group: rows p*32..p*32+32
    const int cg = warp >> 2;       // col group: cols cg*64..cg*64+64
    const int bc = blockIdx.x;
    const int branch = blockIdx.y;
    const int b = bc >> 7;

    const float* rel = branch ? clone_rel : thorn_rel;
    const float* bias = branch ? b_clone : b_thorn;
    const int* mask = branch ? clone_mask : thorn_mask;
    const float* baseCol = branch ? g_A1 : g_base_thorn;
    float* out = branch ? g_clone_agg : g_thorn_agg;
    const uint32_t* __restrict__ Bp = g_Bpack[3 + branch];

    char* reg = sA[p];

    // Stage: this warp loads 16 rows (local rows cg*16..cg*16+16 of region p).
    {
        const int lrow0 = cg * 16;
        const float4* Arow = (const float4*)(rel + (size_t)bc * 16384
                                             + (size_t)(p * 32 + lrow0) * 128);
#pragma unroll
        for (int i = 0; i < 16; i++) {
            float4 v = ldg_stream(Arow + i * 32 + lane);
            __half2 h01 = __floats2half2_rn(v.x, v.y);
            __half2 h23 = __floats2half2_rn(v.z, v.w);
            *(uint2*)&reg[(lrow0 + i) * WSTRIDE + lane * 8] =
                make_uint2(*(uint32_t*)&h01, *(uint32_t*)&h23);
        }
    }
    // Pair-local named barrier (warps p and p+4), 64 threads.
    asm volatile("bar.sync %0, 64;" :: "r"(p + 1) : "memory");

    // ldmatrix addresses for the two 16-row tiles of region p.
    uint32_t reg_u32;
    asm("{ .reg .u64 t; cvta.to.shared.u64 t, %1; cvt.u32.u64 %0, t; }"
        : "=r"(reg_u32) : "l"((const void*)reg));
    const int mi = lane >> 3;
    const int lr = lane & 7;
    const int arow = (mi & 1) * 8 + lr;
    const int acolh = (mi >> 1) * 8;
    uint32_t lm0 = reg_u32 + arow * WSTRIDE + acolh * 2;
    uint32_t lm1 = lm0 + 16 * WSTRIDE;

    // acc[mt][nt][c]: mt 0/1 row tiles, nt 0..7 col tiles (cols cg*64+nt*8)
    float acc[2][8][4];
#pragma unroll
    for (int mt = 0; mt < 2; mt++)
#pragma unroll
        for (int nt = 0; nt < 8; nt++)
#pragma unroll
            for (int c = 0; c < 4; c++) acc[mt][nt][c] = 0.0f;

#pragma unroll
    for (int ks = 0; ks < 8; ks++) {
        uint32_t a00, a01, a02, a03, a10, a11, a12, a13;
        asm volatile("ldmatrix.sync.aligned.m8n8.x4.shared.b16 {%0,%1,%2,%3}, [%4];"
                     : "=r"(a00), "=r"(a01), "=r"(a02), "=r"(a03)
                     : "r"(lm0 + ks * 32));
        asm volatile("ldmatrix.sync.aligned.m8n8.x4.shared.b16 {%0,%1,%2,%3}, [%4];"
                     : "=r"(a10), "=r"(a11), "=r"(a12), "=r"(a13)
                     : "r"(lm1 + ks * 32));
        const uint32_t* bbase = Bp + ks * 1024 + (cg * 4) * 128 + lane * 4;
#pragma unroll
        for (int ntp = 0; ntp < 4; ntp++) {
            uint4 bb = *(const uint4*)&bbase[ntp * 128];
            mma2(bb, a00, a01, a02, a03, acc[0][2 * ntp], acc[0][2 * ntp + 1]);
            mma2(bb, a10, a11, a12, a13, acc[1][2 * ntp], acc[1][2 * ntp + 1]);
        }
    }

    // Epilogue. Warp rows: wr + mt*16 + g and +8; cols: c0 + nt*8 + 2*t4.
    const int wr = p * 32;
    const int c0 = cg * 64;
    int rowi[4] = {wr + g, wr + g + 8, wr + 16 + g, wr + 24 + g};
    float mk[4];
    const float* rtp[4];
#pragma unroll
    for (int q = 0; q < 4; q++) {
        mk[q] = (float)mask[b * 128 + rowi[q]];
        rtp[q] = g_A2 + ((size_t)(b * 128 + rowi[q])) * 128;
    }

#pragma unroll
    for (int nt = 0; nt < 8; nt++) {
        const int n0 = c0 + nt * 8 + 2 * t4;
        float2 bs = *(const float2*)&baseCol[(size_t)bc * 128 + n0];
        float2 bi = *(const float2*)&bias[n0];
        float add0 = bs.x + bi.x;
        float add1 = bs.y + bi.y;
        float c0m = 0.0f, c1m = 0.0f;
#pragma unroll
        for (int mt = 0; mt < 2; mt++) {
            float x0 = acc[mt][nt][0] + add0;
            float x1 = acc[mt][nt][1] + add1;
            float x2 = acc[mt][nt][2] + add0;
            float x3 = acc[mt][nt][3] + add1;
            if (branch) {
                float2 ra = *(const float2*)&rtp[mt * 2][n0];
                float2 rb = *(const float2*)&rtp[mt * 2 + 1][n0];
                x0 += ra.x; x1 += ra.y;
                x2 += rb.x; x3 += rb.y;
            }
            float ma = mk[mt * 2], mb = mk[mt * 2 + 1];
            c0m = fmaxf(c0m, fmaxf(fmaxf(x0, 0.0f) * ma, fmaxf(x2, 0.0f) * mb));
            c1m = fmaxf(c1m, fmaxf(fmaxf(x1, 0.0f) * ma, fmaxf(x3, 0.0f) * mb));
        }
#pragma unroll
        for (int off = 4; off < 32; off <<= 1) {
            c0m = fmaxf(c0m, __shfl_xor_sync(0xFFFFFFFFu, c0m, off));
            c1m = fmaxf(c1m, __shfl_xor_sync(0xFFFFFFFFu, c1m, off));
        }
        if (g == 0) {
            red[warp * 128 + n0] = c0m;
            red[warp * 128 + n0 + 1] = c1m;
        }
    }

    __syncthreads();
    if (tid < 128) {
        // Column tid served by warps with cg == tid>>6, i.e. w = (tid>>6)*4 + 0..3
        int wb = (tid >> 6) * 4;
        float m = fmaxf(fmaxf(red[(wb + 0) * 128 + tid], red[(wb + 1) * 128 + tid]),
                        fmaxf(red[(wb + 2) * 128 + tid], red[(wb + 3) * 128 + tid]));
        out[(size_t)bc * 128 + tid] = m;
    }
}

// ---------------------------------------------------------------------------
// Fused final: out = clone + relu([clone|food|thorn_agg|clone_agg] @ W_agg + b)
// Grid 128, 256 threads = 8 warps; warp w handles slice s = w>>1,
// K-half kh = w&1. Two-phase accumulation into 4 shared buffers (32 KB).
// ---------------------------------------------------------------------------
__global__ void __launch_bounds__(256) final_kernel(
    const float* __restrict__ clone,
    const float* __restrict__ food,
    const float* __restrict__ b_agg,
    float* __restrict__ out)
{
    __shared__ float sacc[4][16 * 128];     // 32 KB

    const int tid = threadIdx.x;
    const int warp = tid >> 5;
    const int lane = tid & 31;
    const int m0 = blockIdx.x * 16;
    const int s = warp >> 1;
    const int kh = warp & 1;

    const float* src = (s == 0) ? clone : (s == 1) ? food
                     : (s == 2) ? g_thorn_agg : g_clone_agg;

    float acc[16][4];
    zero16(acc);
    mma_acc_gmem(src + (size_t)m0 * 128, g_Bpack[5 + s], acc, lane, kh * 4, 4);

    const int g = lane >> 2, t4 = lane & 3;
    if (kh == 0) {
#pragma unroll
        for (int nt = 0; nt < 16; nt++) {
            const int n0 = nt * 8 + 2 * t4;
            *(float2*)&sacc[s][g * 128 + n0]       = make_float2(acc[nt][0], acc[nt][1]);
            *(float2*)&sacc[s][(g + 8) * 128 + n0] = make_float2(acc[nt][2], acc[nt][3]);
        }
    }
    __syncthreads();
    if (kh == 1) {
#pragma unroll
        for (int nt = 0; nt < 16; nt++) {
            const int n0 = nt * 8 + 2 * t4;
            float2 u0 = *(float2*)&sacc[s][g * 128 + n0];
            float2 u1 = *(float2*)&sacc[s][(g + 8) * 128 + n0];
            u0.x += acc[nt][0]; u0.y += acc[nt][1];
            u1.x += acc[nt][2]; u1.y += acc[nt][3];
            *(float2*)&sacc[s][g * 128 + n0]       = u0;
            *(float2*)&sacc[s][(g + 8) * 128 + n0] = u1;
        }
    }
    __syncthreads();

#pragma unroll
    for (int i = 0; i < 8; i++) {
        int e = tid + i * 256;            // 0..2047
        int r = e >> 7, n = e & 127;
        float ssum = sacc[0][e] + sacc[1][e] + sacc[2][e] + sacc[3][e] + b_agg[n];
        size_t o = (size_t)(m0 + r) * 128 + n;
        out[o] = clone[o] + fmaxf(ssum, 0.0f);
    }
}

// ---------------------------------------------------------------------------
// Launch
// ---------------------------------------------------------------------------
extern "C" void kernel_launch(void* const* d_in, const int* in_sizes, int n_in,
                              void* d_out, int out_size)
{
    const float* food       = (const float*)d_in[0];
    const float* thorn_rel  = (const float*)d_in[1];
    const float* clone      = (const float*)d_in[2];
    const float* clone_rel  = (const float*)d_in[3];
    const int*   thorn_mask = (const int*)d_in[4];
    const int*   clone_mask = (const int*)d_in[5];
    const float* W_thorn    = (const float*)d_in[6];
    const float* b_thorn    = (const float*)d_in[7];
    const float* W_clone    = (const float*)d_in[8];
    const float* b_clone    = (const float*)d_in[9];
    const float* W_agg      = (const float*)d_in[10];
    const float* b_agg      = (const float*)d_in[11];
    float* out = (float*)d_out;

    prepack_b_kernel<<<288, 256>>>(W_thorn, W_clone, W_agg);
    precompute_kernel<<<dim3(32, 3), 128>>>(clone);
    relation_mma_kernel<<<dim3(BC, 2), 256>>>(thorn_rel, clone_rel,
                                              b_thorn, b_clone,
                                              thorn_mask, clone_mask);
    final_kernel<<<128, 256>>>(clone, food, b_agg, out);
}

// round 14
// speedup vs baseline: 1.1829x; 1.0876x over previous
#include <cuda_runtime.h>
#include <cuda_fp16.h>
#include <cstdint>

#define NB 16
#define BC 2048
#define WSTRIDE 272   // bytes per A row in smem (256 data + 16 pad)

// ---------------------------------------------------------------------------
// Scratch (static device globals)
// ---------------------------------------------------------------------------
__device__ float g_base_thorn[BC * 128];
__device__ float g_A1[BC * 128];
__device__ float g_A2[BC * 128];
__device__ float g_thorn_agg[BC * 128];
__device__ float g_clone_agg[BC * 128];
// Prepacked fp16 B fragments for mma.m16n8k16, nt-pairs adjacent.
// 9 matrices: 0=W_thorn[:H], 1=W_clone[:H], 2=W_clone[H:2H],
//             3=W_thorn[H:2H], 4=W_clone[2H:3H], 5..8=W_agg slices.
// layout [m][ ((ks*8 + ntp)*32 + lane)*4 + j ]  -> 8192 u32 per matrix
__device__ uint32_t g_Bpack[9][8192];

// ---------------------------------------------------------------------------
// Prepack all weights into fp16 fragment order.
// ---------------------------------------------------------------------------
__global__ void __launch_bounds__(256) prepack_b_kernel(
    const float* __restrict__ W_thorn,
    const float* __restrict__ W_clone,
    const float* __restrict__ W_agg)
{
    int gidx = blockIdx.x * 256 + threadIdx.x;    // 0 .. 9*8192-1
    int m = gidx >> 13;
    int idx = gidx & 8191;
    const float* W;
    switch (m) {
        case 0: W = W_thorn; break;
        case 1: W = W_clone; break;
        case 2: W = W_clone + 16384; break;
        case 3: W = W_thorn + 16384; break;
        case 4: W = W_clone + 32768; break;
        default: W = W_agg + (m - 5) * 16384; break;
    }
    int j    = idx & 3;
    int lane = (idx >> 2) & 31;
    int ntp  = (idx >> 7) & 7;
    int ks   = idx >> 10;
    int t4 = lane & 3, g = lane >> 2;
    int nt = 2 * ntp + (j >> 1);
    int k = ks * 16 + (j & 1) * 8 + 2 * t4;
    int n = nt * 8 + g;
    __half2 h = __floats2half2_rn(W[k * 128 + n], W[(k + 1) * 128 + n]);
    g_Bpack[m][idx] = *(uint32_t*)&h;
}

// ---------------------------------------------------------------------------
// MMA helpers
// ---------------------------------------------------------------------------
__device__ __forceinline__ void mma2(const uint4& bb,
                                     uint32_t a0, uint32_t a1, uint32_t a2, uint32_t a3,
                                     float* acc0, float* acc1) {
    asm volatile(
        "mma.sync.aligned.m16n8k16.row.col.f32.f16.f16.f32 "
        "{%0,%1,%2,%3}, {%4,%5,%6,%7}, {%8,%9}, {%0,%1,%2,%3};"
        : "+f"(acc0[0]), "+f"(acc0[1]), "+f"(acc0[2]), "+f"(acc0[3])
        : "r"(a0), "r"(a1), "r"(a2), "r"(a3), "r"(bb.x), "r"(bb.y));
    asm volatile(
        "mma.sync.aligned.m16n8k16.row.col.f32.f16.f16.f32 "
        "{%0,%1,%2,%3}, {%4,%5,%6,%7}, {%8,%9}, {%0,%1,%2,%3};"
        : "+f"(acc1[0]), "+f"(acc1[1]), "+f"(acc1[2]), "+f"(acc1[3])
        : "r"(a0), "r"(a1), "r"(a2), "r"(a3), "r"(bb.z), "r"(bb.w));
}

// A-tile load: stream-through (no L1 allocation) so B fragments stay L1-resident.
__device__ __forceinline__ float4 ldg_stream(const float4* p) {
    float4 v;
    asm volatile("ld.global.nc.L1::no_allocate.v4.f32 {%0,%1,%2,%3}, [%4];"
                 : "=f"(v.x), "=f"(v.y), "=f"(v.z), "=f"(v.w)
                 : "l"(__cvta_generic_to_global(p)));
    return v;
}

// Warp-level GEMM accumulate over ks steps [ks0, ks0+nks), A fp32 in gmem.
__device__ __forceinline__ void mma_acc_gmem(
    const float* __restrict__ A0,
    const uint32_t* __restrict__ Bp,
    float acc[16][4], int lane, int ks0, int nks)
{
    const int g = lane >> 2, t4 = lane & 3;
    const float* p0 = A0 + g * 128 + ks0 * 16 + 2 * t4;
    const float* p1 = A0 + (g + 8) * 128 + ks0 * 16 + 2 * t4;
    float2 f00 = *(const float2*)(p0);
    float2 f10 = *(const float2*)(p1);
    float2 f01 = *(const float2*)(p0 + 8);
    float2 f11 = *(const float2*)(p1 + 8);
#pragma unroll
    for (int kk = 0; kk < 8; kk++) {
        if (kk >= nks) break;
        __half2 h;
        uint32_t a0, a1, a2, a3;
        h = __floats2half2_rn(f00.x, f00.y); a0 = *(uint32_t*)&h;
        h = __floats2half2_rn(f10.x, f10.y); a1 = *(uint32_t*)&h;
        h = __floats2half2_rn(f01.x, f01.y); a2 = *(uint32_t*)&h;
        h = __floats2half2_rn(f11.x, f11.y); a3 = *(uint32_t*)&h;
        if (kk + 1 < nks) {
            f00 = *(const float2*)(p0 + 16 * (kk + 1));
            f10 = *(const float2*)(p1 + 16 * (kk + 1));
            f01 = *(const float2*)(p0 + 16 * (kk + 1) + 8);
            f11 = *(const float2*)(p1 + 16 * (kk + 1) + 8);
        }
        const uint32_t* bbase = Bp + (ks0 + kk) * 1024 + lane * 4;
#pragma unroll
        for (int ntp = 0; ntp < 8; ntp++) {
            uint4 bb = *(const uint4*)&bbase[ntp * 128];
            mma2(bb, a0, a1, a2, a3, acc[2 * ntp], acc[2 * ntp + 1]);
        }
    }
}

__device__ __forceinline__ void zero16(float acc[16][4]) {
#pragma unroll
    for (int nt = 0; nt < 16; nt++)
#pragma unroll
        for (int c = 0; c < 4; c++) acc[nt][c] = 0.0f;
}

// ---------------------------------------------------------------------------
// Precompute: clone @ {W_thorn[:H], W_clone[:H], W_clone[H:2H]}
// ---------------------------------------------------------------------------
__global__ void __launch_bounds__(128) precompute_kernel(
    const float* __restrict__ clone)
{
    const int tid = threadIdx.x;
    const int warp = tid >> 5;
    const int lane = tid & 31;
    const int y = blockIdx.y;
    const int m0 = blockIdx.x * 64 + warp * 16;

    float* out = (y == 0) ? g_base_thorn : (y == 1) ? g_A1 : g_A2;

    float acc[16][4];
    zero16(acc);
    mma_acc_gmem(clone + (size_t)m0 * 128, g_Bpack[y], acc, lane, 0, 8);

    const int g = lane >> 2, t4 = lane & 3;
    const int r0 = m0 + g, r1 = r0 + 8;
#pragma unroll
    for (int nt = 0; nt < 16; nt++) {
        const int n0 = nt * 8 + 2 * t4;
        *(float2*)&out[(size_t)r0 * 128 + n0] = make_float2(acc[nt][0], acc[nt][1]);
        *(float2*)&out[(size_t)r1 * 128 + n0] = make_float2(acc[nt][2], acc[nt][3]);
    }
}

// ---------------------------------------------------------------------------
// Relation kernel: one block per (bc, branch). 256 threads = 8 warps.
// Warp tiling 128 rows x 16 cols: warp w owns cols w*16..w*16+16, ALL rows.
// Block stages the full 128x128 A tile (warp w stages rows w*16..+16,
// burst of 16 LDG.128 L1-no-allocate), one __syncthreads, then compute.
// The max-over-rows reduction is fully warp-local (8 m-tiles in registers
// + one shfl chain) -> NO block syncs after staging, no smem reduction.
// B: one uint4 per ks per warp (8 LDG.128 total).
// ---------------------------------------------------------------------------
__global__ void __launch_bounds__(256) relation_mma_kernel(
    const float* __restrict__ thorn_rel,
    const float* __restrict__ clone_rel,
    const float* __restrict__ b_thorn,
    const float* __restrict__ b_clone,
    const int* __restrict__ thorn_mask,
    const int* __restrict__ clone_mask)
{
    __shared__ __align__(16) char sA[128 * WSTRIDE];   // 34816 B

    const int tid = threadIdx.x;
    const int warp = tid >> 5;
    const int lane = tid & 31;
    const int g = lane >> 2;
    const int t4 = lane & 3;
    const int bc = blockIdx.x;
    const int branch = blockIdx.y;
    const int b = bc >> 7;

    const float* rel = branch ? clone_rel : thorn_rel;
    const float* bias = branch ? b_clone : b_thorn;
    const int* mask = branch ? clone_mask : thorn_mask;
    const float* baseCol = branch ? g_A1 : g_base_thorn;
    float* out = branch ? g_clone_agg : g_thorn_agg;
    const uint32_t* __restrict__ Bp = g_Bpack[3 + branch];

    // Stage: warp w loads rows w*16..w*16+16 (lane = float4 column index).
    {
        const float4* Arow = (const float4*)(rel + (size_t)bc * 16384
                                             + (size_t)(warp * 16) * 128);
#pragma unroll
        for (int i = 0; i < 16; i++) {
            float4 v = ldg_stream(Arow + i * 32 + lane);
            __half2 h01 = __floats2half2_rn(v.x, v.y);
            __half2 h23 = __floats2half2_rn(v.z, v.w);
            *(uint2*)&sA[(warp * 16 + i) * WSTRIDE + lane * 8] =
                make_uint2(*(uint32_t*)&h01, *(uint32_t*)&h23);
        }
    }
    __syncthreads();

    // ldmatrix per-lane base (within a 16-row m-tile).
    uint32_t sA_u32;
    asm("{ .reg .u64 t; cvta.to.shared.u64 t, %1; cvt.u32.u64 %0, t; }"
        : "=r"(sA_u32) : "l"((const void*)sA));
    const int mi = lane >> 3;
    const int lr = lane & 7;
    const int arow = (mi & 1) * 8 + lr;
    const int acolh = (mi >> 1) * 8;
    const uint32_t lm_base = sA_u32 + arow * WSTRIDE + acolh * 2;

    // acc[mt][nt][c]: mt 0..7 row tiles (rows mt*16..), nt 0..1 col tiles
    // (cols warp*16 + nt*8). Lane holds rows mt*16+g / +8, cols n0, n0+1.
    float acc[8][2][4];
#pragma unroll
    for (int mt = 0; mt < 8; mt++)
#pragma unroll
        for (int nt = 0; nt < 2; nt++)
#pragma unroll
            for (int c = 0; c < 4; c++) acc[mt][nt][c] = 0.0f;

#pragma unroll
    for (int ks = 0; ks < 8; ks++) {
        uint4 bb = *(const uint4*)&Bp[ks * 1024 + warp * 128 + lane * 4];
#pragma unroll
        for (int mt = 0; mt < 8; mt++) {
            uint32_t a0, a1, a2, a3;
            asm volatile("ldmatrix.sync.aligned.m8n8.x4.shared.b16 {%0,%1,%2,%3}, [%4];"
                         : "=r"(a0), "=r"(a1), "=r"(a2), "=r"(a3)
                         : "r"(lm_base + (uint32_t)(mt * 16 * WSTRIDE + ks * 32)));
            mma2(bb, a0, a1, a2, a3, acc[mt][0], acc[mt][1]);
        }
    }

    // Warp-local epilogue: max over all 128 rows for the warp's 16 cols.
#pragma unroll
    for (int nt = 0; nt < 2; nt++) {
        const int n0 = warp * 16 + nt * 8 + 2 * t4;
        float2 bs = *(const float2*)&baseCol[(size_t)bc * 128 + n0];
        float2 bi = *(const float2*)&bias[n0];
        float add0 = bs.x + bi.x;
        float add1 = bs.y + bi.y;
        float c0m = 0.0f, c1m = 0.0f;
#pragma unroll
        for (int mt = 0; mt < 8; mt++) {
            const int r0 = mt * 16 + g;
            const int r1 = r0 + 8;
            float m0v = (float)mask[b * 128 + r0];
            float m1v = (float)mask[b * 128 + r1];
            float x0 = acc[mt][nt][0] + add0;
            float x1 = acc[mt][nt][1] + add1;
            float x2 = acc[mt][nt][2] + add0;
            float x3 = acc[mt][nt][3] + add1;
            if (branch) {
                float2 ra = *(const float2*)&g_A2[((size_t)(b * 128 + r0)) * 128 + n0];
                float2 rb = *(const float2*)&g_A2[((size_t)(b * 128 + r1)) * 128 + n0];
                x0 += ra.x; x1 += ra.y;
                x2 += rb.x; x3 += rb.y;
            }
            c0m = fmaxf(c0m, fmaxf(fmaxf(x0, 0.0f) * m0v, fmaxf(x2, 0.0f) * m1v));
            c1m = fmaxf(c1m, fmaxf(fmaxf(x1, 0.0f) * m0v, fmaxf(x3, 0.0f) * m1v));
        }
        // Reduce over g (lane bits 2..4): offsets 4, 8, 16.
#pragma unroll
        for (int off = 4; off < 32; off <<= 1) {
            c0m = fmaxf(c0m, __shfl_xor_sync(0xFFFFFFFFu, c0m, off));
            c1m = fmaxf(c1m, __shfl_xor_sync(0xFFFFFFFFu, c1m, off));
        }
        if (g == 0)
            *(float2*)&out[(size_t)bc * 128 + n0] = make_float2(c0m, c1m);
    }
}

// ---------------------------------------------------------------------------
// Fused final: out = clone + relu([clone|food|thorn_agg|clone_agg] @ W_agg + b)
// Grid 128, 256 threads = 8 warps; warp w handles slice s = w>>1,
// K-half kh = w&1. Two-phase accumulation into 4 shared buffers (32 KB).
// ---------------------------------------------------------------------------
__global__ void __launch_bounds__(256) final_kernel(
    const float* __restrict__ clone,
    const float* __restrict__ food,
    const float* __restrict__ b_agg,
    float* __restrict__ out)
{
    __shared__ float sacc[4][16 * 128];     // 32 KB

    const int tid = threadIdx.x;
    const int warp = tid >> 5;
    const int lane = tid & 31;
    const int m0 = blockIdx.x * 16;
    const int s = warp >> 1;
    const int kh = warp & 1;

    const float* src = (s == 0) ? clone : (s == 1) ? food
                     : (s == 2) ? g_thorn_agg : g_clone_agg;

    float acc[16][4];
    zero16(acc);
    mma_acc_gmem(src + (size_t)m0 * 128, g_Bpack[5 + s], acc, lane, kh * 4, 4);

    const int g = lane >> 2, t4 = lane & 3;
    if (kh == 0) {
#pragma unroll
        for (int nt = 0; nt < 16; nt++) {
            const int n0 = nt * 8 + 2 * t4;
            *(float2*)&sacc[s][g * 128 + n0]       = make_float2(acc[nt][0], acc[nt][1]);
            *(float2*)&sacc[s][(g + 8) * 128 + n0] = make_float2(acc[nt][2], acc[nt][3]);
        }
    }
    __syncthreads();
    if (kh == 1) {
#pragma unroll
        for (int nt = 0; nt < 16; nt++) {
            const int n0 = nt * 8 + 2 * t4;
            float2 u0 = *(float2*)&sacc[s][g * 128 + n0];
            float2 u1 = *(float2*)&sacc[s][(g + 8) * 128 + n0];
            u0.x += acc[nt][0]; u0.y += acc[nt][1];
            u1.x += acc[nt][2]; u1.y += acc[nt][3];
            *(float2*)&sacc[s][g * 128 + n0]       = u0;
            *(float2*)&sacc[s][(g + 8) * 128 + n0] = u1;
        }
    }
    __syncthreads();

#pragma unroll
    for (int i = 0; i < 8; i++) {
        int e = tid + i * 256;            // 0..2047
        int r = e >> 7, n = e & 127;
        float ssum = sacc[0][e] + sacc[1][e] + sacc[2][e] + sacc[3][e] + b_agg[n];
        size_t o = (size_t)(m0 + r) * 128 + n;
        out[o] = clone[o] + fmaxf(ssum, 0.0f);
    }
}

// ---------------------------------------------------------------------------
// Launch
// ---------------------------------------------------------------------------
extern "C" void kernel_launch(void* const* d_in, const int* in_sizes, int n_in,
                              void* d_out, int out_size)
{
    const float* food       = (const float*)d_in[0];
    const float* thorn_rel  = (const float*)d_in[1];
    const float* clone      = (const float*)d_in[2];
    const float* clone_rel  = (const float*)d_in[3];
    const int*   thorn_mask = (const int*)d_in[4];
    const int*   clone_mask = (const int*)d_in[5];
    const float* W_thorn    = (const float*)d_in[6];
    const float* b_thorn    = (const float*)d_in[7];
    const float* W_clone    = (const float*)d_in[8];
    const float* b_clone    = (const float*)d_in[9];
    const float* W_agg      = (const float*)d_in[10];
    const float* b_agg      = (const float*)d_in[11];
    float* out = (float*)d_out;

    prepack_b_kernel<<<288, 256>>>(W_thorn, W_clone, W_agg);
    precompute_kernel<<<dim3(32, 3), 128>>>(clone);
    relation_mma_kernel<<<dim3(BC, 2), 256>>>(thorn_rel, clone_rel,
                                              b_thorn, b_clone,
                                              thorn_mask, clone_mask);
    final_kernel<<<128, 256>>>(clone, food, b_agg, out);
}

// round 15
// speedup vs baseline: 1.1881x; 1.0043x over previous
#include <cuda_runtime.h>
#include <cuda_fp16.h>
#include <cstdint>

#define NB 16
#define BC 2048
#define WSTRIDE 272   // bytes per A row in smem (256 data + 16 pad)

// ---------------------------------------------------------------------------
// Scratch (static device globals)
// ---------------------------------------------------------------------------
__device__ float g_base_thorn[BC * 128];
__device__ float g_A1[BC * 128];
__device__ float g_A2[BC * 128];
__device__ float g_thorn_agg[BC * 128];
__device__ float g_clone_agg[BC * 128];
// Prepacked fp16 B fragments for mma.m16n8k16, nt-pairs adjacent.
// 9 matrices: 0=W_thorn[:H], 1=W_clone[:H], 2=W_clone[H:2H],
//             3=W_thorn[H:2H], 4=W_clone[2H:3H], 5..8=W_agg slices.
// layout [m][ ((ks*8 + ntp)*32 + lane)*4 + j ]  -> 8192 u32 per matrix
__device__ uint32_t g_Bpack[9][8192];

// ---------------------------------------------------------------------------
// Prepack all weights into fp16 fragment order.
// ---------------------------------------------------------------------------
__global__ void __launch_bounds__(256) prepack_b_kernel(
    const float* __restrict__ W_thorn,
    const float* __restrict__ W_clone,
    const float* __restrict__ W_agg)
{
    int gidx = blockIdx.x * 256 + threadIdx.x;    // 0 .. 9*8192-1
    int m = gidx >> 13;
    int idx = gidx & 8191;
    const float* W;
    switch (m) {
        case 0: W = W_thorn; break;
        case 1: W = W_clone; break;
        case 2: W = W_clone + 16384; break;
        case 3: W = W_thorn + 16384; break;
        case 4: W = W_clone + 32768; break;
        default: W = W_agg + (m - 5) * 16384; break;
    }
    int j    = idx & 3;
    int lane = (idx >> 2) & 31;
    int ntp  = (idx >> 7) & 7;
    int ks   = idx >> 10;
    int t4 = lane & 3, g = lane >> 2;
    int nt = 2 * ntp + (j >> 1);
    int k = ks * 16 + (j & 1) * 8 + 2 * t4;
    int n = nt * 8 + g;
    __half2 h = __floats2half2_rn(W[k * 128 + n], W[(k + 1) * 128 + n]);
    g_Bpack[m][idx] = *(uint32_t*)&h;
}

// ---------------------------------------------------------------------------
// MMA helpers
// ---------------------------------------------------------------------------
__device__ __forceinline__ void mma2(const uint4& bb,
                                     uint32_t a0, uint32_t a1, uint32_t a2, uint32_t a3,
                                     float* acc0, float* acc1) {
    asm volatile(
        "mma.sync.aligned.m16n8k16.row.col.f32.f16.f16.f32 "
        "{%0,%1,%2,%3}, {%4,%5,%6,%7}, {%8,%9}, {%0,%1,%2,%3};"
        : "+f"(acc0[0]), "+f"(acc0[1]), "+f"(acc0[2]), "+f"(acc0[3])
        : "r"(a0), "r"(a1), "r"(a2), "r"(a3), "r"(bb.x), "r"(bb.y));
    asm volatile(
        "mma.sync.aligned.m16n8k16.row.col.f32.f16.f16.f32 "
        "{%0,%1,%2,%3}, {%4,%5,%6,%7}, {%8,%9}, {%0,%1,%2,%3};"
        : "+f"(acc1[0]), "+f"(acc1[1]), "+f"(acc1[2]), "+f"(acc1[3])
        : "r"(a0), "r"(a1), "r"(a2), "r"(a3), "r"(bb.z), "r"(bb.w));
}

// A-tile load: stream-through (no L1 allocation) so B fragments stay L1-resident.
__device__ __forceinline__ float4 ldg_stream(const float4* p) {
    float4 v;
    asm volatile("ld.global.nc.L1::no_allocate.v4.f32 {%0,%1,%2,%3}, [%4];"
                 : "=f"(v.x), "=f"(v.y), "=f"(v.z), "=f"(v.w)
                 : "l"(__cvta_generic_to_global(p)));
    return v;
}

// Warp-level partial GEMM: NKS k-steps from ks0, NNTP nt-pairs from ntp0.
// A fp32 in gmem (warp's first row at A0); acc[2*NNTP][4].
template<int NKS, int NNTP>
__device__ __forceinline__ void mma_acc_part(
    const float* __restrict__ A0,
    const uint32_t* __restrict__ Bp,
    float acc[][4], int lane, int ks0, int ntp0)
{
    const int g = lane >> 2, t4 = lane & 3;
    const float* p0 = A0 + g * 128 + ks0 * 16 + 2 * t4;
    const float* p1 = A0 + (g + 8) * 128 + ks0 * 16 + 2 * t4;
    float2 f00 = *(const float2*)(p0);
    float2 f10 = *(const float2*)(p1);
    float2 f01 = *(const float2*)(p0 + 8);
    float2 f11 = *(const float2*)(p1 + 8);
#pragma unroll
    for (int kk = 0; kk < NKS; kk++) {
        __half2 h;
        uint32_t a0, a1, a2, a3;
        h = __floats2half2_rn(f00.x, f00.y); a0 = *(uint32_t*)&h;
        h = __floats2half2_rn(f10.x, f10.y); a1 = *(uint32_t*)&h;
        h = __floats2half2_rn(f01.x, f01.y); a2 = *(uint32_t*)&h;
        h = __floats2half2_rn(f11.x, f11.y); a3 = *(uint32_t*)&h;
        if (kk + 1 < NKS) {
            f00 = *(const float2*)(p0 + 16 * (kk + 1));
            f10 = *(const float2*)(p1 + 16 * (kk + 1));
            f01 = *(const float2*)(p0 + 16 * (kk + 1) + 8);
            f11 = *(const float2*)(p1 + 16 * (kk + 1) + 8);
        }
        const uint32_t* bbase = Bp + (ks0 + kk) * 1024 + ntp0 * 128 + lane * 4;
#pragma unroll
        for (int ntp = 0; ntp < NNTP; ntp++) {
            uint4 bb = *(const uint4*)&bbase[ntp * 128];
            mma2(bb, a0, a1, a2, a3, acc[2 * ntp], acc[2 * ntp + 1]);
        }
    }
}

// ---------------------------------------------------------------------------
// Precompute: clone @ {W_thorn[:H], W_clone[:H], W_clone[H:2H]}
// Grid (64, 3): block bx -> rows (bx>>1)*64, col half bx&1. 128 threads.
// ---------------------------------------------------------------------------
__global__ void __launch_bounds__(128) precompute_kernel(
    const float* __restrict__ clone)
{
    const int tid = threadIdx.x;
    const int warp = tid >> 5;
    const int lane = tid & 31;
    const int y = blockIdx.y;
    const int m0 = (blockIdx.x >> 1) * 64 + warp * 16;
    const int ch = blockIdx.x & 1;

    float* out = (y == 0) ? g_base_thorn : (y == 1) ? g_A1 : g_A2;

    float acc[8][4];
#pragma unroll
    for (int i = 0; i < 8; i++)
#pragma unroll
        for (int c = 0; c < 4; c++) acc[i][c] = 0.0f;
    mma_acc_part<8, 4>(clone + (size_t)m0 * 128, g_Bpack[y], acc, lane, 0, ch * 4);

    const int g = lane >> 2, t4 = lane & 3;
    const int r0 = m0 + g, r1 = r0 + 8;
#pragma unroll
    for (int nt = 0; nt < 8; nt++) {
        const int n0 = ch * 64 + nt * 8 + 2 * t4;
        *(float2*)&out[(size_t)r0 * 128 + n0] = make_float2(acc[nt][0], acc[nt][1]);
        *(float2*)&out[(size_t)r1 * 128 + n0] = make_float2(acc[nt][2], acc[nt][3]);
    }
}

// ---------------------------------------------------------------------------
// Relation kernel: one block per (bc, branch). 256 threads = 8 warps.
// Warp tiling 128 rows x 16 cols: warp w owns cols w*16..w*16+16, ALL rows.
// Block stages the full 128x128 A tile (warp w stages rows w*16..+16,
// burst of 16 LDG.128 L1-no-allocate), one __syncthreads, then compute.
// Max-over-rows reduction fully warp-local. B: 8 LDG.128 per warp.
// (At the legacy mma.sync issue ceiling — do not touch.)
// ---------------------------------------------------------------------------
__global__ void __launch_bounds__(256) relation_mma_kernel(
    const float* __restrict__ thorn_rel,
    const float* __restrict__ clone_rel,
    const float* __restrict__ b_thorn,
    const float* __restrict__ b_clone,
    const int* __restrict__ thorn_mask,
    const int* __restrict__ clone_mask)
{
    __shared__ __align__(16) char sA[128 * WSTRIDE];   // 34816 B

    const int tid = threadIdx.x;
    const int warp = tid >> 5;
    const int lane = tid & 31;
    const int g = lane >> 2;
    const int t4 = lane & 3;
    const int bc = blockIdx.x;
    const int branch = blockIdx.y;
    const int b = bc >> 7;

    const float* rel = branch ? clone_rel : thorn_rel;
    const float* bias = branch ? b_clone : b_thorn;
    const int* mask = branch ? clone_mask : thorn_mask;
    const float* baseCol = branch ? g_A1 : g_base_thorn;
    float* out = branch ? g_clone_agg : g_thorn_agg;
    const uint32_t* __restrict__ Bp = g_Bpack[3 + branch];

    // Stage: warp w loads rows w*16..w*16+16 (lane = float4 column index).
    {
        const float4* Arow = (const float4*)(rel + (size_t)bc * 16384
                                             + (size_t)(warp * 16) * 128);
#pragma unroll
        for (int i = 0; i < 16; i++) {
            float4 v = ldg_stream(Arow + i * 32 + lane);
            __half2 h01 = __floats2half2_rn(v.x, v.y);
            __half2 h23 = __floats2half2_rn(v.z, v.w);
            *(uint2*)&sA[(warp * 16 + i) * WSTRIDE + lane * 8] =
                make_uint2(*(uint32_t*)&h01, *(uint32_t*)&h23);
        }
    }
    __syncthreads();

    // ldmatrix per-lane base (within a 16-row m-tile).
    uint32_t sA_u32;
    asm("{ .reg .u64 t; cvta.to.shared.u64 t, %1; cvt.u32.u64 %0, t; }"
        : "=r"(sA_u32) : "l"((const void*)sA));
    const int mi = lane >> 3;
    const int lr = lane & 7;
    const int arow = (mi & 1) * 8 + lr;
    const int acolh = (mi >> 1) * 8;
    const uint32_t lm_base = sA_u32 + arow * WSTRIDE + acolh * 2;

    // acc[mt][nt][c]: mt 0..7 row tiles, nt 0..1 col tiles (cols warp*16+nt*8)
    float acc[8][2][4];
#pragma unroll
    for (int mt = 0; mt < 8; mt++)
#pragma unroll
        for (int nt = 0; nt < 2; nt++)
#pragma unroll
            for (int c = 0; c < 4; c++) acc[mt][nt][c] = 0.0f;

#pragma unroll
    for (int ks = 0; ks < 8; ks++) {
        uint4 bb = *(const uint4*)&Bp[ks * 1024 + warp * 128 + lane * 4];
#pragma unroll
        for (int mt = 0; mt < 8; mt++) {
            uint32_t a0, a1, a2, a3;
            asm volatile("ldmatrix.sync.aligned.m8n8.x4.shared.b16 {%0,%1,%2,%3}, [%4];"
                         : "=r"(a0), "=r"(a1), "=r"(a2), "=r"(a3)
                         : "r"(lm_base + (uint32_t)(mt * 16 * WSTRIDE + ks * 32)));
            mma2(bb, a0, a1, a2, a3, acc[mt][0], acc[mt][1]);
        }
    }

    // Warp-local epilogue: max over all 128 rows for the warp's 16 cols.
#pragma unroll
    for (int nt = 0; nt < 2; nt++) {
        const int n0 = warp * 16 + nt * 8 + 2 * t4;
        float2 bs = *(const float2*)&baseCol[(size_t)bc * 128 + n0];
        float2 bi = *(const float2*)&bias[n0];
        float add0 = bs.x + bi.x;
        float add1 = bs.y + bi.y;
        float c0m = 0.0f, c1m = 0.0f;
#pragma unroll
        for (int mt = 0; mt < 8; mt++) {
            const int r0 = mt * 16 + g;
            const int r1 = r0 + 8;
            float m0v = (float)mask[b * 128 + r0];
            float m1v = (float)mask[b * 128 + r1];
            float x0 = acc[mt][nt][0] + add0;
            float x1 = acc[mt][nt][1] + add1;
            float x2 = acc[mt][nt][2] + add0;
            float x3 = acc[mt][nt][3] + add1;
            if (branch) {
                float2 ra = *(const float2*)&g_A2[((size_t)(b * 128 + r0)) * 128 + n0];
                float2 rb = *(const float2*)&g_A2[((size_t)(b * 128 + r1)) * 128 + n0];
                x0 += ra.x; x1 += ra.y;
                x2 += rb.x; x3 += rb.y;
            }
            c0m = fmaxf(c0m, fmaxf(fmaxf(x0, 0.0f) * m0v, fmaxf(x2, 0.0f) * m1v));
            c1m = fmaxf(c1m, fmaxf(fmaxf(x1, 0.0f) * m0v, fmaxf(x3, 0.0f) * m1v));
        }
#pragma unroll
        for (int off = 4; off < 32; off <<= 1) {
            c0m = fmaxf(c0m, __shfl_xor_sync(0xFFFFFFFFu, c0m, off));
            c1m = fmaxf(c1m, __shfl_xor_sync(0xFFFFFFFFu, c1m, off));
        }
        if (g == 0)
            *(float2*)&out[(size_t)bc * 128 + n0] = make_float2(c0m, c1m);
    }
}

// ---------------------------------------------------------------------------
// Fused final: out = clone + relu([clone|food|thorn_agg|clone_agg] @ W_agg + b)
// Grid (128, 2): block = 16 rows x 64 cols (col half = blockIdx.y).
// 256 threads = 8 warps; warp w -> slice s = w>>1, K-half kh = w&1.
// Two-phase accumulation into 4 shared buffers (16 KB).
// ---------------------------------------------------------------------------
__global__ void __launch_bounds__(256) final_kernel(
    const float* __restrict__ clone,
    const float* __restrict__ food,
    const float* __restrict__ b_agg,
    float* __restrict__ out)
{
    __shared__ float sacc[4][16 * 64];      // 16 KB

    const int tid = threadIdx.x;
    const int warp = tid >> 5;
    const int lane = tid & 31;
    const int m0 = blockIdx.x * 16;
    const int ch = blockIdx.y;
    const int s = warp >> 1;
    const int kh = warp & 1;

    const float* src = (s == 0) ? clone : (s == 1) ? food
                     : (s == 2) ? g_thorn_agg : g_clone_agg;

    float acc[8][4];
#pragma unroll
    for (int i = 0; i < 8; i++)
#pragma unroll
        for (int c = 0; c < 4; c++) acc[i][c] = 0.0f;
    mma_acc_part<4, 4>(src + (size_t)m0 * 128, g_Bpack[5 + s], acc, lane,
                       kh * 4, ch * 4);

    const int g = lane >> 2, t4 = lane & 3;
    if (kh == 0) {
#pragma unroll
        for (int nt = 0; nt < 8; nt++) {
            const int lc = nt * 8 + 2 * t4;
            *(float2*)&sacc[s][g * 64 + lc]       = make_float2(acc[nt][0], acc[nt][1]);
            *(float2*)&sacc[s][(g + 8) * 64 + lc] = make_float2(acc[nt][2], acc[nt][3]);
        }
    }
    __syncthreads();
    if (kh == 1) {
#pragma unroll
        for (int nt = 0; nt < 8; nt++) {
            const int lc = nt * 8 + 2 * t4;
            float2 u0 = *(float2*)&sacc[s][g * 64 + lc];
            float2 u1 = *(float2*)&sacc[s][(g + 8) * 64 + lc];
            u0.x += acc[nt][0]; u0.y += acc[nt][1];
            u1.x += acc[nt][2]; u1.y += acc[nt][3];
            *(float2*)&sacc[s][g * 64 + lc]       = u0;
            *(float2*)&sacc[s][(g + 8) * 64 + lc] = u1;
        }
    }
    __syncthreads();

#pragma unroll
    for (int i = 0; i < 4; i++) {
        int e = tid + i * 256;            // 0..1023
        int r = e >> 6, lc = e & 63;
        int n = ch * 64 + lc;
        float ssum = sacc[0][e] + sacc[1][e] + sacc[2][e] + sacc[3][e] + b_agg[n];
        size_t o = (size_t)(m0 + r) * 128 + n;
        out[o] = clone[o] + fmaxf(ssum, 0.0f);
    }
}

// ---------------------------------------------------------------------------
// Launch
// ---------------------------------------------------------------------------
extern "C" void kernel_launch(void* const* d_in, const int* in_sizes, int n_in,
                              void* d_out, int out_size)
{
    const float* food       = (const float*)d_in[0];
    const float* thorn_rel  = (const float*)d_in[1];
    const float* clone      = (const float*)d_in[2];
    const float* clone_rel  = (const float*)d_in[3];
    const int*   thorn_mask = (const int*)d_in[4];
    const int*   clone_mask = (const int*)d_in[5];
    const float* W_thorn    = (const float*)d_in[6];
    const float* b_thorn    = (const float*)d_in[7];
    const float* W_clone    = (const float*)d_in[8];
    const float* b_clone    = (const float*)d_in[9];
    const float* W_agg      = (const float*)d_in[10];
    const float* b_agg      = (const float*)d_in[11];
    float* out = (float*)d_out;

    prepack_b_kernel<<<288, 256>>>(W_thorn, W_clone, W_agg);
    precompute_kernel<<<dim3(64, 3), 128>>>(clone);
    relation_mma_kernel<<<dim3(BC, 2), 256>>>(thorn_rel, clone_rel,
                                              b_thorn, b_clone,
                                              thorn_mask, clone_mask);
    final_kernel<<<dim3(128, 2), 256>>>(clone, food, b_agg, out);
}

// round 16
// speedup vs baseline: 1.2080x; 1.0168x over previous
#include <cuda_runtime.h>
#include <cuda_fp16.h>
#include <cstdint>

#define NB 16
#define BC 2048
#define WSTRIDE 272   // bytes per A row in smem (256 data + 16 pad)

// ---------------------------------------------------------------------------
// Scratch (static device globals)
// ---------------------------------------------------------------------------
__device__ float g_base_thorn[BC * 128];
__device__ float g_A1[BC * 128];
__device__ float g_A2[BC * 128];
__device__ float g_thorn_agg[BC * 128];
__device__ float g_clone_agg[BC * 128];
// Prepacked fp16 B fragments for mma.m16n8k16, nt-pairs adjacent.
// 9 matrices: 0=W_thorn[:H], 1=W_clone[:H], 2=W_clone[H:2H],
//             3=W_thorn[H:2H], 4=W_clone[2H:3H], 5..8=W_agg slices.
// layout [m][ ((ks*8 + ntp)*32 + lane)*4 + j ]  -> 8192 u32 per matrix
__device__ uint32_t g_Bpack[9][8192];

// ---------------------------------------------------------------------------
// Prepack all weights into fp16 fragment order.
// ---------------------------------------------------------------------------
__global__ void __launch_bounds__(256) prepack_b_kernel(
    const float* __restrict__ W_thorn,
    const float* __restrict__ W_clone,
    const float* __restrict__ W_agg)
{
    int gidx = blockIdx.x * 256 + threadIdx.x;    // 0 .. 9*8192-1
    int m = gidx >> 13;
    int idx = gidx & 8191;
    const float* W;
    switch (m) {
        case 0: W = W_thorn; break;
        case 1: W = W_clone; break;
        case 2: W = W_clone + 16384; break;
        case 3: W = W_thorn + 16384; break;
        case 4: W = W_clone + 32768; break;
        default: W = W_agg + (m - 5) * 16384; break;
    }
    int j    = idx & 3;
    int lane = (idx >> 2) & 31;
    int ntp  = (idx >> 7) & 7;
    int ks   = idx >> 10;
    int t4 = lane & 3, g = lane >> 2;
    int nt = 2 * ntp + (j >> 1);
    int k = ks * 16 + (j & 1) * 8 + 2 * t4;
    int n = nt * 8 + g;
    __half2 h = __floats2half2_rn(W[k * 128 + n], W[(k + 1) * 128 + n]);
    g_Bpack[m][idx] = *(uint32_t*)&h;
}

// ---------------------------------------------------------------------------
// MMA helpers
// ---------------------------------------------------------------------------
__device__ __forceinline__ void mma2(const uint4& bb,
                                     uint32_t a0, uint32_t a1, uint32_t a2, uint32_t a3,
                                     float* acc0, float* acc1) {
    asm volatile(
        "mma.sync.aligned.m16n8k16.row.col.f32.f16.f16.f32 "
        "{%0,%1,%2,%3}, {%4,%5,%6,%7}, {%8,%9}, {%0,%1,%2,%3};"
        : "+f"(acc0[0]), "+f"(acc0[1]), "+f"(acc0[2]), "+f"(acc0[3])
        : "r"(a0), "r"(a1), "r"(a2), "r"(a3), "r"(bb.x), "r"(bb.y));
    asm volatile(
        "mma.sync.aligned.m16n8k16.row.col.f32.f16.f16.f32 "
        "{%0,%1,%2,%3}, {%4,%5,%6,%7}, {%8,%9}, {%0,%1,%2,%3};"
        : "+f"(acc1[0]), "+f"(acc1[1]), "+f"(acc1[2]), "+f"(acc1[3])
        : "r"(a0), "r"(a1), "r"(a2), "r"(a3), "r"(bb.z), "r"(bb.w));
}

// A-tile load: stream-through (no L1 allocation) so B fragments stay L1-resident.
__device__ __forceinline__ float4 ldg_stream(const float4* p) {
    float4 v;
    asm volatile("ld.global.nc.L1::no_allocate.v4.f32 {%0,%1,%2,%3}, [%4];"
                 : "=f"(v.x), "=f"(v.y), "=f"(v.z), "=f"(v.w)
                 : "l"(__cvta_generic_to_global(p)));
    return v;
}

// Warp-level partial GEMM: NKS k-steps from ks0, NNTP nt-pairs from ntp0.
// A fp32 in gmem (warp's first row at A0); acc[2*NNTP][4].
template<int NKS, int NNTP>
__device__ __forceinline__ void mma_acc_part(
    const float* __restrict__ A0,
    const uint32_t* __restrict__ Bp,
    float acc[][4], int lane, int ks0, int ntp0)
{
    const int g = lane >> 2, t4 = lane & 3;
    const float* p0 = A0 + g * 128 + ks0 * 16 + 2 * t4;
    const float* p1 = A0 + (g + 8) * 128 + ks0 * 16 + 2 * t4;
    float2 f00 = *(const float2*)(p0);
    float2 f10 = *(const float2*)(p1);
    float2 f01 = *(const float2*)(p0 + 8);
    float2 f11 = *(const float2*)(p1 + 8);
#pragma unroll
    for (int kk = 0; kk < NKS; kk++) {
        __half2 h;
        uint32_t a0, a1, a2, a3;
        h = __floats2half2_rn(f00.x, f00.y); a0 = *(uint32_t*)&h;
        h = __floats2half2_rn(f10.x, f10.y); a1 = *(uint32_t*)&h;
        h = __floats2half2_rn(f01.x, f01.y); a2 = *(uint32_t*)&h;
        h = __floats2half2_rn(f11.x, f11.y); a3 = *(uint32_t*)&h;
        if (kk + 1 < NKS) {
            f00 = *(const float2*)(p0 + 16 * (kk + 1));
            f10 = *(const float2*)(p1 + 16 * (kk + 1));
            f01 = *(const float2*)(p0 + 16 * (kk + 1) + 8);
            f11 = *(const float2*)(p1 + 16 * (kk + 1) + 8);
        }
        const uint32_t* bbase = Bp + (ks0 + kk) * 1024 + ntp0 * 128 + lane * 4;
#pragma unroll
        for (int ntp = 0; ntp < NNTP; ntp++) {
            uint4 bb = *(const uint4*)&bbase[ntp * 128];
            mma2(bb, a0, a1, a2, a3, acc[2 * ntp], acc[2 * ntp + 1]);
        }
    }
}

// ---------------------------------------------------------------------------
// Precompute: clone @ {W_thorn[:H], W_clone[:H], W_clone[H:2H]}
// Grid (64, 3): block bx -> rows (bx>>1)*64, col half bx&1. 128 threads.
// ---------------------------------------------------------------------------
__global__ void __launch_bounds__(128) precompute_kernel(
    const float* __restrict__ clone)
{
    const int tid = threadIdx.x;
    const int warp = tid >> 5;
    const int lane = tid & 31;
    const int y = blockIdx.y;
    const int m0 = (blockIdx.x >> 1) * 64 + warp * 16;
    const int ch = blockIdx.x & 1;

    float* out = (y == 0) ? g_base_thorn : (y == 1) ? g_A1 : g_A2;

    float acc[8][4];
#pragma unroll
    for (int i = 0; i < 8; i++)
#pragma unroll
        for (int c = 0; c < 4; c++) acc[i][c] = 0.0f;
    mma_acc_part<8, 4>(clone + (size_t)m0 * 128, g_Bpack[y], acc, lane, 0, ch * 4);

    const int g = lane >> 2, t4 = lane & 3;
    const int r0 = m0 + g, r1 = r0 + 8;
#pragma unroll
    for (int nt = 0; nt < 8; nt++) {
        const int n0 = ch * 64 + nt * 8 + 2 * t4;
        *(float2*)&out[(size_t)r0 * 128 + n0] = make_float2(acc[nt][0], acc[nt][1]);
        *(float2*)&out[(size_t)r1 * 128 + n0] = make_float2(acc[nt][2], acc[nt][3]);
    }
}

// ---------------------------------------------------------------------------
// Relation kernel: one block per (bc, branch). 256 threads = 8 warps.
// Warp tiling 128 rows x 16 cols: warp w owns cols w*16..w*16+16, ALL rows.
// Block stages the full 128x128 A tile (warp w stages rows w*16..+16,
// burst of 16 LDG.128 L1-no-allocate), one __syncthreads, then compute.
// B for the whole warp tile = 8 uint4 -> PRELOADED into registers before the
// MMA loop, so the inner loop is pure LDSM + HMMA (no memory scoreboard).
// Max-over-rows reduction fully warp-local.
// ---------------------------------------------------------------------------
__global__ void __launch_bounds__(256, 2) relation_mma_kernel(
    const float* __restrict__ thorn_rel,
    const float* __restrict__ clone_rel,
    const float* __restrict__ b_thorn,
    const float* __restrict__ b_clone,
    const int* __restrict__ thorn_mask,
    const int* __restrict__ clone_mask)
{
    __shared__ __align__(16) char sA[128 * WSTRIDE];   // 34816 B

    const int tid = threadIdx.x;
    const int warp = tid >> 5;
    const int lane = tid & 31;
    const int g = lane >> 2;
    const int t4 = lane & 3;
    const int bc = blockIdx.x;
    const int branch = blockIdx.y;
    const int b = bc >> 7;

    const float* rel = branch ? clone_rel : thorn_rel;
    const float* bias = branch ? b_clone : b_thorn;
    const int* mask = branch ? clone_mask : thorn_mask;
    const float* baseCol = branch ? g_A1 : g_base_thorn;
    float* out = branch ? g_clone_agg : g_thorn_agg;
    const uint32_t* __restrict__ Bp = g_Bpack[3 + branch];

    // Stage: warp w loads rows w*16..w*16+16 (lane = float4 column index).
    {
        const float4* Arow = (const float4*)(rel + (size_t)bc * 16384
                                             + (size_t)(warp * 16) * 128);
#pragma unroll
        for (int i = 0; i < 16; i++) {
            float4 v = ldg_stream(Arow + i * 32 + lane);
            __half2 h01 = __floats2half2_rn(v.x, v.y);
            __half2 h23 = __floats2half2_rn(v.z, v.w);
            *(uint2*)&sA[(warp * 16 + i) * WSTRIDE + lane * 8] =
                make_uint2(*(uint32_t*)&h01, *(uint32_t*)&h23);
        }
    }
    __syncthreads();

    // Preload the warp's entire B working set (8 uint4 = 32 regs).
    uint4 bb[8];
#pragma unroll
    for (int ks = 0; ks < 8; ks++)
        bb[ks] = *(const uint4*)&Bp[ks * 1024 + warp * 128 + lane * 4];

    // ldmatrix per-lane base (within a 16-row m-tile).
    uint32_t sA_u32;
    asm("{ .reg .u64 t; cvta.to.shared.u64 t, %1; cvt.u32.u64 %0, t; }"
        : "=r"(sA_u32) : "l"((const void*)sA));
    const int mi = lane >> 3;
    const int lr = lane & 7;
    const int arow = (mi & 1) * 8 + lr;
    const int acolh = (mi >> 1) * 8;
    const uint32_t lm_base = sA_u32 + arow * WSTRIDE + acolh * 2;

    // acc[mt][nt][c]: mt 0..7 row tiles, nt 0..1 col tiles (cols warp*16+nt*8)
    float acc[8][2][4];
#pragma unroll
    for (int mt = 0; mt < 8; mt++)
#pragma unroll
        for (int nt = 0; nt < 2; nt++)
#pragma unroll
            for (int c = 0; c < 4; c++) acc[mt][nt][c] = 0.0f;

#pragma unroll
    for (int ks = 0; ks < 8; ks++) {
#pragma unroll
        for (int mt = 0; mt < 8; mt++) {
            uint32_t a0, a1, a2, a3;
            asm volatile("ldmatrix.sync.aligned.m8n8.x4.shared.b16 {%0,%1,%2,%3}, [%4];"
                         : "=r"(a0), "=r"(a1), "=r"(a2), "=r"(a3)
                         : "r"(lm_base + (uint32_t)(mt * 16 * WSTRIDE + ks * 32)));
            mma2(bb[ks], a0, a1, a2, a3, acc[mt][0], acc[mt][1]);
        }
    }

    // Warp-local epilogue: max over all 128 rows for the warp's 16 cols.
#pragma unroll
    for (int nt = 0; nt < 2; nt++) {
        const int n0 = warp * 16 + nt * 8 + 2 * t4;
        float2 bs = *(const float2*)&baseCol[(size_t)bc * 128 + n0];
        float2 bi = *(const float2*)&bias[n0];
        float add0 = bs.x + bi.x;
        float add1 = bs.y + bi.y;
        float c0m = 0.0f, c1m = 0.0f;
#pragma unroll
        for (int mt = 0; mt < 8; mt++) {
            const int r0 = mt * 16 + g;
            const int r1 = r0 + 8;
            float m0v = (float)mask[b * 128 + r0];
            float m1v = (float)mask[b * 128 + r1];
            float x0 = acc[mt][nt][0] + add0;
            float x1 = acc[mt][nt][1] + add1;
            float x2 = acc[mt][nt][2] + add0;
            float x3 = acc[mt][nt][3] + add1;
            if (branch) {
                float2 ra = *(const float2*)&g_A2[((size_t)(b * 128 + r0)) * 128 + n0];
                float2 rb = *(const float2*)&g_A2[((size_t)(b * 128 + r1)) * 128 + n0];
                x0 += ra.x; x1 += ra.y;
                x2 += rb.x; x3 += rb.y;
            }
            c0m = fmaxf(c0m, fmaxf(fmaxf(x0, 0.0f) * m0v, fmaxf(x2, 0.0f) * m1v));
            c1m = fmaxf(c1m, fmaxf(fmaxf(x1, 0.0f) * m0v, fmaxf(x3, 0.0f) * m1v));
        }
#pragma unroll
        for (int off = 4; off < 32; off <<= 1) {
            c0m = fmaxf(c0m, __shfl_xor_sync(0xFFFFFFFFu, c0m, off));
            c1m = fmaxf(c1m, __shfl_xor_sync(0xFFFFFFFFu, c1m, off));
        }
        if (g == 0)
            *(float2*)&out[(size_t)bc * 128 + n0] = make_float2(c0m, c1m);
    }
}

// ---------------------------------------------------------------------------
// Fused final: out = clone + relu([clone|food|thorn_agg|clone_agg] @ W_agg + b)
// Grid (128, 2): block = 16 rows x 64 cols (col half = blockIdx.y).
// 256 threads = 8 warps; warp w -> slice s = w>>1, K-half kh = w&1.
// Two-phase accumulation into 4 shared buffers (16 KB).
// ---------------------------------------------------------------------------
__global__ void __launch_bounds__(256) final_kernel(
    const float* __restrict__ clone,
    const float* __restrict__ food,
    const float* __restrict__ b_agg,
    float* __restrict__ out)
{
    __shared__ float sacc[4][16 * 64];      // 16 KB

    const int tid = threadIdx.x;
    const int warp = tid >> 5;
    const int lane = tid & 31;
    const int m0 = blockIdx.x * 16;
    const int ch = blockIdx.y;
    const int s = warp >> 1;
    const int kh = warp & 1;

    const float* src = (s == 0) ? clone : (s == 1) ? food
                     : (s == 2) ? g_thorn_agg : g_clone_agg;

    float acc[8][4];
#pragma unroll
    for (int i = 0; i < 8; i++)
#pragma unroll
        for (int c = 0; c < 4; c++) acc[i][c] = 0.0f;
    mma_acc_part<4, 4>(src + (size_t)m0 * 128, g_Bpack[5 + s], acc, lane,
                       kh * 4, ch * 4);

    const int g = lane >> 2, t4 = lane & 3;
    if (kh == 0) {
#pragma unroll
        for (int nt = 0; nt < 8; nt++) {
            const int lc = nt * 8 + 2 * t4;
            *(float2*)&sacc[s][g * 64 + lc]       = make_float2(acc[nt][0], acc[nt][1]);
            *(float2*)&sacc[s][(g + 8) * 64 + lc] = make_float2(acc[nt][2], acc[nt][3]);
        }
    }
    __syncthreads();
    if (kh == 1) {
#pragma unroll
        for (int nt = 0; nt < 8; nt++) {
            const int lc = nt * 8 + 2 * t4;
            float2 u0 = *(float2*)&sacc[s][g * 64 + lc];
            float2 u1 = *(float2*)&sacc[s][(g + 8) * 64 + lc];
            u0.x += acc[nt][0]; u0.y += acc[nt][1];
            u1.x += acc[nt][2]; u1.y += acc[nt][3];
            *(float2*)&sacc[s][g * 64 + lc]       = u0;
            *(float2*)&sacc[s][(g + 8) * 64 + lc] = u1;
        }
    }
    __syncthreads();

#pragma unroll
    for (int i = 0; i < 4; i++) {
        int e = tid + i * 256;            // 0..1023
        int r = e >> 6, lc = e & 63;
        int n = ch * 64 + lc;
        float ssum = sacc[0][e] + sacc[1][e] + sacc[2][e] + sacc[3][e] + b_agg[n];
        size_t o = (size_t)(m0 + r) * 128 + n;
        out[o] = clone[o] + fmaxf(ssum, 0.0f);
    }
}

// ---------------------------------------------------------------------------
// Launch
// ---------------------------------------------------------------------------
extern "C" void kernel_launch(void* const* d_in, const int* in_sizes, int n_in,
                              void* d_out, int out_size)
{
    const float* food       = (const float*)d_in[0];
    const float* thorn_rel  = (const float*)d_in[1];
    const float* clone      = (const float*)d_in[2];
    const float* clone_rel  = (const float*)d_in[3];
    const int*   thorn_mask = (const int*)d_in[4];
    const int*   clone_mask = (const int*)d_in[5];
    const float* W_thorn    = (const float*)d_in[6];
    const float* b_thorn    = (const float*)d_in[7];
    const float* W_clone    = (const float*)d_in[8];
    const float* b_clone    = (const float*)d_in[9];
    const float* W_agg      = (const float*)d_in[10];
    const float* b_agg      = (const float*)d_in[11];
    float* out = (float*)d_out;

    prepack_b_kernel<<<288, 256>>>(W_thorn, W_clone, W_agg);
    precompute_kernel<<<dim3(64, 3), 128>>>(clone);
    relation_mma_kernel<<<dim3(BC, 2), 256>>>(thorn_rel, clone_rel,
                                              b_thorn, b_clone,
                                              thorn_mask, clone_mask);
    final_kernel<<<dim3(128, 2), 256>>>(clone, food, b_agg, out);
}

// round 17
// speedup vs baseline: 1.2105x; 1.0021x over previous
#include <cuda_runtime.h>
#include <cuda_fp16.h>
#include <cstdint>

#define NB 16
#define BC 2048
#define WSTRIDE 272   // bytes per A row in smem (256 data + 16 pad)

// ---------------------------------------------------------------------------
// Scratch (static device globals)
// ---------------------------------------------------------------------------
__device__ float g_base_thorn[BC * 128];
__device__ float g_A1[BC * 128];
__device__ float g_A2[BC * 128];
__device__ float g_thorn_agg[BC * 128];
__device__ float g_clone_agg[BC * 128];
// Prepacked fp16 B fragments for mma.m16n8k16, nt-pairs adjacent.
// 9 matrices: 0=W_thorn[:H], 1=W_clone[:H], 2=W_clone[H:2H],
//             3=W_thorn[H:2H], 4=W_clone[2H:3H], 5..8=W_agg slices.
// layout [m][ ((ks*8 + ntp)*32 + lane)*4 + j ]  -> 8192 u32 per matrix
__device__ uint32_t g_Bpack[9][8192];

// ---------------------------------------------------------------------------
// Prepack all weights into fp16 fragment order.
// ---------------------------------------------------------------------------
__global__ void __launch_bounds__(256) prepack_b_kernel(
    const float* __restrict__ W_thorn,
    const float* __restrict__ W_clone,
    const float* __restrict__ W_agg)
{
    int gidx = blockIdx.x * 256 + threadIdx.x;    // 0 .. 9*8192-1
    int m = gidx >> 13;
    int idx = gidx & 8191;
    const float* W;
    switch (m) {
        case 0: W = W_thorn; break;
        case 1: W = W_clone; break;
        case 2: W = W_clone + 16384; break;
        case 3: W = W_thorn + 16384; break;
        case 4: W = W_clone + 32768; break;
        default: W = W_agg + (m - 5) * 16384; break;
    }
    int j    = idx & 3;
    int lane = (idx >> 2) & 31;
    int ntp  = (idx >> 7) & 7;
    int ks   = idx >> 10;
    int t4 = lane & 3, g = lane >> 2;
    int nt = 2 * ntp + (j >> 1);
    int k = ks * 16 + (j & 1) * 8 + 2 * t4;
    int n = nt * 8 + g;
    __half2 h = __floats2half2_rn(W[k * 128 + n], W[(k + 1) * 128 + n]);
    g_Bpack[m][idx] = *(uint32_t*)&h;
}

// ---------------------------------------------------------------------------
// MMA helpers
// ---------------------------------------------------------------------------
__device__ __forceinline__ void mma2(const uint4& bb,
                                     uint32_t a0, uint32_t a1, uint32_t a2, uint32_t a3,
                                     float* acc0, float* acc1) {
    asm volatile(
        "mma.sync.aligned.m16n8k16.row.col.f32.f16.f16.f32 "
        "{%0,%1,%2,%3}, {%4,%5,%6,%7}, {%8,%9}, {%0,%1,%2,%3};"
        : "+f"(acc0[0]), "+f"(acc0[1]), "+f"(acc0[2]), "+f"(acc0[3])
        : "r"(a0), "r"(a1), "r"(a2), "r"(a3), "r"(bb.x), "r"(bb.y));
    asm volatile(
        "mma.sync.aligned.m16n8k16.row.col.f32.f16.f16.f32 "
        "{%0,%1,%2,%3}, {%4,%5,%6,%7}, {%8,%9}, {%0,%1,%2,%3};"
        : "+f"(acc1[0]), "+f"(acc1[1]), "+f"(acc1[2]), "+f"(acc1[3])
        : "r"(a0), "r"(a1), "r"(a2), "r"(a3), "r"(bb.z), "r"(bb.w));
}

// A-tile load: stream-through (no L1 allocation) so B fragments stay L1-resident.
__device__ __forceinline__ float4 ldg_stream(const float4* p) {
    float4 v;
    asm volatile("ld.global.nc.L1::no_allocate.v4.f32 {%0,%1,%2,%3}, [%4];"
                 : "=f"(v.x), "=f"(v.y), "=f"(v.z), "=f"(v.w)
                 : "l"(__cvta_generic_to_global(p)));
    return v;
}

// Warp-level partial GEMM with FRONT-LOADED A: all NKS k-steps' A fragments
// are issued before any compute (MLP = 4*NKS), so DRAM latency is paid once.
// B loads stay in-loop (L1 hits). acc[2*NNTP][4].
template<int NKS, int NNTP>
__device__ __forceinline__ void mma_acc_front(
    const float* __restrict__ A0,
    const uint32_t* __restrict__ Bp,
    float acc[][4], int lane, int ks0, int ntp0)
{
    const int g = lane >> 2, t4 = lane & 3;
    const float* p0 = A0 + g * 128 + ks0 * 16 + 2 * t4;
    const float* p1 = A0 + (g + 8) * 128 + ks0 * 16 + 2 * t4;
    float2 f[NKS][4];
#pragma unroll
    for (int kk = 0; kk < NKS; kk++) {
        f[kk][0] = *(const float2*)(p0 + 16 * kk);
        f[kk][1] = *(const float2*)(p1 + 16 * kk);
        f[kk][2] = *(const float2*)(p0 + 16 * kk + 8);
        f[kk][3] = *(const float2*)(p1 + 16 * kk + 8);
    }
#pragma unroll
    for (int kk = 0; kk < NKS; kk++) {
        __half2 h;
        uint32_t a0, a1, a2, a3;
        h = __floats2half2_rn(f[kk][0].x, f[kk][0].y); a0 = *(uint32_t*)&h;
        h = __floats2half2_rn(f[kk][1].x, f[kk][1].y); a1 = *(uint32_t*)&h;
        h = __floats2half2_rn(f[kk][2].x, f[kk][2].y); a2 = *(uint32_t*)&h;
        h = __floats2half2_rn(f[kk][3].x, f[kk][3].y); a3 = *(uint32_t*)&h;
        const uint32_t* bbase = Bp + (ks0 + kk) * 1024 + ntp0 * 128 + lane * 4;
#pragma unroll
        for (int ntp = 0; ntp < NNTP; ntp++) {
            uint4 bb = *(const uint4*)&bbase[ntp * 128];
            mma2(bb, a0, a1, a2, a3, acc[2 * ntp], acc[2 * ntp + 1]);
        }
    }
}

// ---------------------------------------------------------------------------
// Precompute: clone @ {W_thorn[:H], W_clone[:H], W_clone[H:2H]}
// Grid (64, 3): block bx -> rows (bx>>1)*64, col half bx&1. 128 threads.
// ---------------------------------------------------------------------------
__global__ void __launch_bounds__(128) precompute_kernel(
    const float* __restrict__ clone)
{
    const int tid = threadIdx.x;
    const int warp = tid >> 5;
    const int lane = tid & 31;
    const int y = blockIdx.y;
    const int m0 = (blockIdx.x >> 1) * 64 + warp * 16;
    const int ch = blockIdx.x & 1;

    float* out = (y == 0) ? g_base_thorn : (y == 1) ? g_A1 : g_A2;

    float acc[8][4];
#pragma unroll
    for (int i = 0; i < 8; i++)
#pragma unroll
        for (int c = 0; c < 4; c++) acc[i][c] = 0.0f;
    mma_acc_front<8, 4>(clone + (size_t)m0 * 128, g_Bpack[y], acc, lane, 0, ch * 4);

    const int g = lane >> 2, t4 = lane & 3;
    const int r0 = m0 + g, r1 = r0 + 8;
#pragma unroll
    for (int nt = 0; nt < 8; nt++) {
        const int n0 = ch * 64 + nt * 8 + 2 * t4;
        *(float2*)&out[(size_t)r0 * 128 + n0] = make_float2(acc[nt][0], acc[nt][1]);
        *(float2*)&out[(size_t)r1 * 128 + n0] = make_float2(acc[nt][2], acc[nt][3]);
    }
}

// ---------------------------------------------------------------------------
// Relation kernel: one block per (bc, branch). 256 threads = 8 warps.
// Warp tiling 128 rows x 16 cols: warp w owns cols w*16..w*16+16, ALL rows.
// Block stages the full 128x128 A tile (warp w stages rows w*16..+16,
// burst of 16 LDG.128 L1-no-allocate), one __syncthreads, then compute.
// B for the whole warp tile = 8 uint4 -> PRELOADED into registers before the
// MMA loop, so the inner loop is pure LDSM + HMMA (no memory scoreboard).
// Max-over-rows reduction fully warp-local. (At mma.sync ceiling — frozen.)
// ---------------------------------------------------------------------------
__global__ void __launch_bounds__(256, 2) relation_mma_kernel(
    const float* __restrict__ thorn_rel,
    const float* __restrict__ clone_rel,
    const float* __restrict__ b_thorn,
    const float* __restrict__ b_clone,
    const int* __restrict__ thorn_mask,
    const int* __restrict__ clone_mask)
{
    __shared__ __align__(16) char sA[128 * WSTRIDE];   // 34816 B

    const int tid = threadIdx.x;
    const int warp = tid >> 5;
    const int lane = tid & 31;
    const int g = lane >> 2;
    const int t4 = lane & 3;
    const int bc = blockIdx.x;
    const int branch = blockIdx.y;
    const int b = bc >> 7;

    const float* rel = branch ? clone_rel : thorn_rel;
    const float* bias = branch ? b_clone : b_thorn;
    const int* mask = branch ? clone_mask : thorn_mask;
    const float* baseCol = branch ? g_A1 : g_base_thorn;
    float* out = branch ? g_clone_agg : g_thorn_agg;
    const uint32_t* __restrict__ Bp = g_Bpack[3 + branch];

    // Stage: warp w loads rows w*16..w*16+16 (lane = float4 column index).
    {
        const float4* Arow = (const float4*)(rel + (size_t)bc * 16384
                                             + (size_t)(warp * 16) * 128);
#pragma unroll
        for (int i = 0; i < 16; i++) {
            float4 v = ldg_stream(Arow + i * 32 + lane);
            __half2 h01 = __floats2half2_rn(v.x, v.y);
            __half2 h23 = __floats2half2_rn(v.z, v.w);
            *(uint2*)&sA[(warp * 16 + i) * WSTRIDE + lane * 8] =
                make_uint2(*(uint32_t*)&h01, *(uint32_t*)&h23);
        }
    }
    __syncthreads();

    // Preload the warp's entire B working set (8 uint4 = 32 regs).
    uint4 bb[8];
#pragma unroll
    for (int ks = 0; ks < 8; ks++)
        bb[ks] = *(const uint4*)&Bp[ks * 1024 + warp * 128 + lane * 4];

    // ldmatrix per-lane base (within a 16-row m-tile).
    uint32_t sA_u32;
    asm("{ .reg .u64 t; cvta.to.shared.u64 t, %1; cvt.u32.u64 %0, t; }"
        : "=r"(sA_u32) : "l"((const void*)sA));
    const int mi = lane >> 3;
    const int lr = lane & 7;
    const int arow = (mi & 1) * 8 + lr;
    const int acolh = (mi >> 1) * 8;
    const uint32_t lm_base = sA_u32 + arow * WSTRIDE + acolh * 2;

    // acc[mt][nt][c]: mt 0..7 row tiles, nt 0..1 col tiles (cols warp*16+nt*8)
    float acc[8][2][4];
#pragma unroll
    for (int mt = 0; mt < 8; mt++)
#pragma unroll
        for (int nt = 0; nt < 2; nt++)
#pragma unroll
            for (int c = 0; c < 4; c++) acc[mt][nt][c] = 0.0f;

#pragma unroll
    for (int ks = 0; ks < 8; ks++) {
#pragma unroll
        for (int mt = 0; mt < 8; mt++) {
            uint32_t a0, a1, a2, a3;
            asm volatile("ldmatrix.sync.aligned.m8n8.x4.shared.b16 {%0,%1,%2,%3}, [%4];"
                         : "=r"(a0), "=r"(a1), "=r"(a2), "=r"(a3)
                         : "r"(lm_base + (uint32_t)(mt * 16 * WSTRIDE + ks * 32)));
            mma2(bb[ks], a0, a1, a2, a3, acc[mt][0], acc[mt][1]);
        }
    }

    // Warp-local epilogue: max over all 128 rows for the warp's 16 cols.
#pragma unroll
    for (int nt = 0; nt < 2; nt++) {
        const int n0 = warp * 16 + nt * 8 + 2 * t4;
        float2 bs = *(const float2*)&baseCol[(size_t)bc * 128 + n0];
        float2 bi = *(const float2*)&bias[n0];
        float add0 = bs.x + bi.x;
        float add1 = bs.y + bi.y;
        float c0m = 0.0f, c1m = 0.0f;
#pragma unroll
        for (int mt = 0; mt < 8; mt++) {
            const int r0 = mt * 16 + g;
            const int r1 = r0 + 8;
            float m0v = (float)mask[b * 128 + r0];
            float m1v = (float)mask[b * 128 + r1];
            float x0 = acc[mt][nt][0] + add0;
            float x1 = acc[mt][nt][1] + add1;
            float x2 = acc[mt][nt][2] + add0;
            float x3 = acc[mt][nt][3] + add1;
            if (branch) {
                float2 ra = *(const float2*)&g_A2[((size_t)(b * 128 + r0)) * 128 + n0];
                float2 rb = *(const float2*)&g_A2[((size_t)(b * 128 + r1)) * 128 + n0];
                x0 += ra.x; x1 += ra.y;
                x2 += rb.x; x3 += rb.y;
            }
            c0m = fmaxf(c0m, fmaxf(fmaxf(x0, 0.0f) * m0v, fmaxf(x2, 0.0f) * m1v));
            c1m = fmaxf(c1m, fmaxf(fmaxf(x1, 0.0f) * m0v, fmaxf(x3, 0.0f) * m1v));
        }
#pragma unroll
        for (int off = 4; off < 32; off <<= 1) {
            c0m = fmaxf(c0m, __shfl_xor_sync(0xFFFFFFFFu, c0m, off));
            c1m = fmaxf(c1m, __shfl_xor_sync(0xFFFFFFFFu, c1m, off));
        }
        if (g == 0)
            *(float2*)&out[(size_t)bc * 128 + n0] = make_float2(c0m, c1m);
    }
}

// ---------------------------------------------------------------------------
// Fused final: out = clone + relu([clone|food|thorn_agg|clone_agg] @ W_agg + b)
// Grid (128, 2): block = 16 rows x 64 cols (col half = blockIdx.y).
// 256 threads = 8 warps; warp w -> slice s = w>>1, K-half kh = w&1.
// A fragments front-loaded (MLP 16). Two-phase smem accumulation (16 KB).
// ---------------------------------------------------------------------------
__global__ void __launch_bounds__(256) final_kernel(
    const float* __restrict__ clone,
    const float* __restrict__ food,
    const float* __restrict__ b_agg,
    float* __restrict__ out)
{
    __shared__ float sacc[4][16 * 64];      // 16 KB

    const int tid = threadIdx.x;
    const int warp = tid >> 5;
    const int lane = tid & 31;
    const int m0 = blockIdx.x * 16;
    const int ch = blockIdx.y;
    const int s = warp >> 1;
    const int kh = warp & 1;

    const float* src = (s == 0) ? clone : (s == 1) ? food
                     : (s == 2) ? g_thorn_agg : g_clone_agg;

    float acc[8][4];
#pragma unroll
    for (int i = 0; i < 8; i++)
#pragma unroll
        for (int c = 0; c < 4; c++) acc[i][c] = 0.0f;
    mma_acc_front<4, 4>(src + (size_t)m0 * 128, g_Bpack[5 + s], acc, lane,
                        kh * 4, ch * 4);

    const int g = lane >> 2, t4 = lane & 3;
    if (kh == 0) {
#pragma unroll
        for (int nt = 0; nt < 8; nt++) {
            const int lc = nt * 8 + 2 * t4;
            *(float2*)&sacc[s][g * 64 + lc]       = make_float2(acc[nt][0], acc[nt][1]);
            *(float2*)&sacc[s][(g + 8) * 64 + lc] = make_float2(acc[nt][2], acc[nt][3]);
        }
    }
    __syncthreads();
    if (kh == 1) {
#pragma unroll
        for (int nt = 0; nt < 8; nt++) {
            const int lc = nt * 8 + 2 * t4;
            float2 u0 = *(float2*)&sacc[s][g * 64 + lc];
            float2 u1 = *(float2*)&sacc[s][(g + 8) * 64 + lc];
            u0.x += acc[nt][0]; u0.y += acc[nt][1];
            u1.x += acc[nt][2]; u1.y += acc[nt][3];
            *(float2*)&sacc[s][g * 64 + lc]       = u0;
            *(float2*)&sacc[s][(g + 8) * 64 + lc] = u1;
        }
    }
    __syncthreads();

#pragma unroll
    for (int i = 0; i < 4; i++) {
        int e = tid + i * 256;            // 0..1023
        int r = e >> 6, lc = e & 63;
        int n = ch * 64 + lc;
        float ssum = sacc[0][e] + sacc[1][e] + sacc[2][e] + sacc[3][e] + b_agg[n];
        size_t o = (size_t)(m0 + r) * 128 + n;
        out[o] = clone[o] + fmaxf(ssum, 0.0f);
    }
}

// ---------------------------------------------------------------------------
// Launch
// ---------------------------------------------------------------------------
extern "C" void kernel_launch(void* const* d_in, const int* in_sizes, int n_in,
                              void* d_out, int out_size)
{
    const float* food       = (const float*)d_in[0];
    const float* thorn_rel  = (const float*)d_in[1];
    const float* clone      = (const float*)d_in[2];
    const float* clone_rel  = (const float*)d_in[3];
    const int*   thorn_mask = (const int*)d_in[4];
    const int*   clone_mask = (const int*)d_in[5];
    const float* W_thorn    = (const float*)d_in[6];
    const float* b_thorn    = (const float*)d_in[7];
    const float* W_clone    = (const float*)d_in[8];
    const float* b_clone    = (const float*)d_in[9];
    const float* W_agg      = (const float*)d_in[10];
    const float* b_agg      = (const float*)d_in[11];
    float* out = (float*)d_out;

    prepack_b_kernel<<<288, 256>>>(W_thorn, W_clone, W_agg);
    precompute_kernel<<<dim3(64, 3), 128>>>(clone);
    relation_mma_kernel<<<dim3(BC, 2), 256>>>(thorn_rel, clone_rel,
                                              b_thorn, b_clone,
                                              thorn_mask, clone_mask);
    final_kernel<<<dim3(128, 2), 256>>>(clone, food, b_agg, out);
}